// round 13
// baseline (speedup 1.0000x reference)
#include <cuda_runtime.h>
#include <cuda_fp16.h>
#include <math.h>
#include <stdint.h>

#define HW 4096     // 64*64
#define BATCH 8

// ---------------- scratch (static device globals; no allocation) ----------------
__device__ float g_h1  [BATCH*64*HW];
__device__ float g_h2  [BATCH*64*HW];
__device__ float g_h3  [BATCH*64*HW];
__device__ float g_feat[BATCH*64*HW];
__device__ float g_off [BATCH*36*HW];   // ch 0..17 = offset, 18..35 = dc_off
__device__ float g_mask[BATCH*9*HW];
__device__ float g_b36 [36];

// channel-pair-interleaved f16 quads:
// q[(b*C/2 + c2)*HW + pix] = uint4{ pack(c0:x,x+1), pack(c0:y+1 row), pack(c1:...), pack(c1:...) }
__device__ uint4 g_xqi [BATCH*128*HW];  // 64MB (x, 256 ch -> 128 pairs)
__device__ uint4 g_hqi3[BATCH*32*HW];   // 16MB (h3, 64 ch -> 32 pairs)

// f16 fragment-packed weights (each u32 = 2 f16 along K)
__device__ unsigned g_Af[144*16*32*4];
#define MIDA (36*4*32*4)
__device__ unsigned g_Ah2 [MIDA], g_Al2 [MIDA];   // shift-order
__device__ unsigned g_Ah3 [MIDA], g_Al3 [MIDA];   // shift-order
__device__ unsigned g_Ah36[MIDA], g_Al36[MIDA];   // shift-order
__device__ unsigned g_Ahdc[MIDA], g_Aldc[MIDA];   // tap-major (K=kk*64+c)

// ---------------- helpers ------------------------------------------------------------
__device__ __forceinline__ void mma_f16(float* acc, unsigned a0, unsigned a1,
                                        unsigned a2, unsigned a3,
                                        unsigned b0, unsigned b1) {
    asm volatile(
        "mma.sync.aligned.m16n8k16.row.col.f32.f16.f16.f32 "
        "{%0,%1,%2,%3}, {%4,%5,%6,%7}, {%8,%9}, {%0,%1,%2,%3};"
        : "+f"(acc[0]), "+f"(acc[1]), "+f"(acc[2]), "+f"(acc[3])
        : "r"(a0), "r"(a1), "r"(a2), "r"(a3), "r"(b0), "r"(b1));
}

__device__ __forceinline__ void frag_coords(int om, int kk, int& lane, int& reg, int& half) {
    int kpair = kk >> 1;
    half = kk & 1;
    lane = (om & 7) * 4 + (kpair & 3);
    reg = (om >> 3) + ((kpair >> 2) << 1);
}

__device__ __forceinline__ unsigned pack_h2(__half lo, __half hi) {
    return (unsigned)__half_as_ushort(lo) | ((unsigned)__half_as_ushort(hi) << 16);
}

__device__ __forceinline__ float dot2h(float4 w, unsigned qa, unsigned qb) {
    float2 f0 = __half22float2(*reinterpret_cast<__half2*>(&qa));
    float2 f1 = __half22float2(*reinterpret_cast<__half2*>(&qb));
    return w.x * f0.x + w.y * f0.y + w.z * f1.x + w.w * f1.y;
}

// ---------------- weight prep kernels -------------------------------------------------
__global__ void prep_middc_tap(const float* __restrict__ w, unsigned* __restrict__ hi,
                               unsigned* __restrict__ lo) {
    int i = blockIdx.x * blockDim.x + threadIdx.x;
    if (i >= 64 * 576) return;
    int K = i % 576;
    int o = i / 576;
    float v = w[o * 576 + K];
    __half vh = __float2half(v);
    __half vl = __float2half(v - __half2float(vh));
    int c = K / 9, kk = K - c * 9;
    int Kn = kk * 64 + c;
    int kc = Kn >> 4, kwi = Kn & 15;
    int lane, reg, half;
    frag_coords(o & 15, kwi, lane, reg, half);
    size_t base = ((((size_t)kc * 4 + (o >> 4)) * 32 + lane) * 4 + reg) * 2 + half;
    ((__half*)hi)[base] = vh;
    ((__half*)lo)[base] = vl;
}

__global__ void prep_shift_f16(const float* __restrict__ w, unsigned* __restrict__ hi,
                               unsigned* __restrict__ lo, int O) {
    int i = blockIdx.x * blockDim.x + threadIdx.x;
    if (i >= 64 * 576) return;
    int K = i % 576;
    int o = i / 576;
    float v = (o < O) ? w[o * 576 + K] : 0.0f;
    __half vh = __float2half(v);
    __half vl = __float2half(v - __half2float(vh));
    int c = K / 9, kk = K % 9;
    int slab = c >> 5, cl = c & 31;
    int kcg = (slab * 9 + kk) * 2 + (cl >> 4);
    int lane, reg, half;
    frag_coords(o & 15, cl & 15, lane, reg, half);
    size_t base = ((((size_t)kcg * 4 + (o >> 4)) * 32 + lane) * 4 + reg) * 2 + half;
    ((__half*)hi)[base] = vh;
    ((__half*)lo)[base] = vl;
}

__global__ void prep_shift_w36(const float* __restrict__ wa, const float* __restrict__ wb,
                               unsigned* __restrict__ hi, unsigned* __restrict__ lo) {
    int i = blockIdx.x * blockDim.x + threadIdx.x;
    if (i >= 64 * 576) return;
    int K = i % 576;
    int o = i / 576;
    float v = 0.0f;
    if (o < 18) v = wa[o * 576 + K];
    else if (o < 36) v = wb[(o - 18) * 576 + K];
    __half vh = __float2half(v);
    __half vl = __float2half(v - __half2float(vh));
    int c = K / 9, kk = K % 9;
    int slab = c >> 5, cl = c & 31;
    int kcg = (slab * 9 + kk) * 2 + (cl >> 4);
    int lane, reg, half;
    frag_coords(o & 15, cl & 15, lane, reg, half);
    size_t base = ((((size_t)kcg * 4 + (o >> 4)) * 32 + lane) * 4 + reg) * 2 + half;
    ((__half*)hi)[base] = vh;
    ((__half*)lo)[base] = vl;
}

// final: tap-major Kn = kk*256 + c
__global__ void prep_final_f16(const float* __restrict__ w, unsigned* __restrict__ dst) {
    int i = blockIdx.x * blockDim.x + threadIdx.x;
    if (i >= 256 * 2304) return;
    int K = i % 2304;
    int o = i / 2304;
    int c = K / 9, kk = K - c * 9;
    int Kn = kk * 256 + c;
    int kc = Kn >> 4, kwi = Kn & 15;
    int lane, reg, half;
    frag_coords(o & 15, kwi, lane, reg, half);
    size_t base = ((((size_t)kc * 16 + (o >> 4)) * 32 + lane) * 4 + reg) * 2 + half;
    ((__half*)dst)[base] = __float2half(w[i]);
}

__global__ void concat_bias36(const float* __restrict__ a, const float* __restrict__ b,
                              float* __restrict__ dst) {
    int i = threadIdx.x;
    if (i < 18) dst[i] = a[i];
    else if (i < 36) dst[i] = b[i - 18];
}

// ---------------- channel-pair interleaved f16 quad shingle ---------------------------
// dst[(b*C2 + c2)*HW + pix] covers channels 2*c2 and 2*c2+1.
__global__ void quad_h2i(const float* __restrict__ src, uint4* __restrict__ dst,
                         int total, int C2) {
    int i = blockIdx.x * blockDim.x + threadIdx.x;
    if (i >= total) return;
    int pix = i & (HW - 1);
    int bc2 = i >> 12;
    int b = bc2 / C2;
    int c2 = bc2 - b * C2;
    int xx = pix & 63, yy = pix >> 6;
    const float* s0 = src + ((size_t)(b * 2 * C2 + c2 * 2)) * HW;
    const float* s1 = s0 + HW;
    bool okx = (xx < 63), oky = (yy < 63);
    float A0 = s0[pix];
    float B0 = okx ? s0[pix + 1] : 0.0f;
    float C0 = oky ? s0[pix + 64] : 0.0f;
    float D0 = (okx && oky) ? s0[pix + 65] : 0.0f;
    float A1 = s1[pix];
    float B1 = okx ? s1[pix + 1] : 0.0f;
    float C1 = oky ? s1[pix + 64] : 0.0f;
    float D1 = (okx && oky) ? s1[pix + 65] : 0.0f;
    dst[i] = make_uint4(pack_h2(__float2half(A0), __float2half(B0)),
                        pack_h2(__float2half(C0), __float2half(D0)),
                        pack_h2(__float2half(A1), __float2half(B1)),
                        pack_h2(__float2half(C1), __float2half(D1)));
}

// ---------------- 1x1 conv + sigmoid -------------------------------------------------
__global__ void mask_kernel(const float* __restrict__ feat, const float* __restrict__ mw,
                            const float* __restrict__ mb, float* __restrict__ mask) {
    int i = blockIdx.x * blockDim.x + threadIdx.x;
    if (i >= BATCH * HW) return;
    int b = i >> 12;
    int pix = i & (HW - 1);
    float acc[9];
#pragma unroll
    for (int o = 0; o < 9; o++) acc[o] = __ldg(mb + o);
    const float* fp = feat + (size_t)b * 64 * HW + pix;
    for (int c = 0; c < 64; c++) {
        float v = __ldg(fp + c * HW);
#pragma unroll
        for (int o = 0; o < 9; o++) acc[o] += v * __ldg(mw + o * 64 + c);
    }
#pragma unroll
    for (int o = 0; o < 9; o++)
        mask[((size_t)b * 9 + o) * HW + pix] = 1.0f / (1.0f + expf(-acc[o]));
}

// ---------------- sp1: fused resize + conv3x3 (CIN=3) + BN + ReLU, fp32 --------------
__device__ __forceinline__ float resize_at(const float* __restrict__ p, int y, int x) {
    const float scale = 127.0f / 63.0f;
    float ys = y * scale, xs = x * scale;
    float fy = floorf(ys), fx = floorf(xs);
    int y0 = (int)fy, x0 = (int)fx;
    int y1 = min(y0 + 1, 127), x1 = min(x0 + 1, 127);
    float wy = ys - fy, wx = xs - fx;
    return p[y0 * 128 + x0] * (1.0f - wy) * (1.0f - wx)
         + p[y0 * 128 + x1] * (1.0f - wy) * wx
         + p[y1 * 128 + x0] * wy * (1.0f - wx)
         + p[y1 * 128 + x1] * wy * wx;
}

__global__ void __launch_bounds__(256)
sp1_kernel(const float* __restrict__ S, const float* __restrict__ w1,
           const float* __restrict__ e_b, const float* __restrict__ e_s,
           const float* __restrict__ e_o, float* __restrict__ out) {
    __shared__ __align__(16) float s_t[576];
    const int b = blockIdx.y;
    const int tile = blockIdx.x;
    const int tid = threadIdx.x;
    const int o = tid & 63;
    const int pbase = (tid >> 6) * 16;

    float acc[16];
#pragma unroll
    for (int j = 0; j < 16; j++) acc[j] = 0.0f;

    for (int c = 0; c < 3; c++) {
        const float* Sc = S + (size_t)(b * 3 + c) * 128 * 128;
        for (int e = tid; e < 576; e += 256) {
            int k = e >> 6, p = e & 63;
            int yy = tile + k / 3 - 1;
            int xx = p + k % 3 - 1;
            s_t[e] = ((unsigned)yy < 64u && (unsigned)xx < 64u)
                         ? resize_at(Sc, yy, xx) : 0.0f;
        }
        __syncthreads();

        float wv[9];
#pragma unroll
        for (int k = 0; k < 9; k++) wv[k] = __ldg(w1 + o * 27 + c * 9 + k);

#pragma unroll
        for (int k = 0; k < 9; k++) {
            const float4* sp = reinterpret_cast<const float4*>(s_t + k * 64 + pbase);
#pragma unroll
            for (int j4 = 0; j4 < 4; j4++) {
                float4 sv = sp[j4];
                acc[j4 * 4 + 0] += wv[k] * sv.x;
                acc[j4 * 4 + 1] += wv[k] * sv.y;
                acc[j4 * 4 + 2] += wv[k] * sv.z;
                acc[j4 * 4 + 3] += wv[k] * sv.w;
            }
        }
        __syncthreads();
    }

    float bb = __ldg(e_b + o), ssc = __ldg(e_s + o), oof = __ldg(e_o + o);
    float* op = out + ((size_t)b * 64 + o) * HW + tile * 64 + pbase;
#pragma unroll
    for (int j = 0; j < 16; j++)
        op[j] = fmaxf((acc[j] + bb) * ssc + oof, 0.0f);
}

// ---------------- plain conv3x3, shifted-window mma; hi/lo interleaved uint2 ---------
template <int EPI>
__global__ void __launch_bounds__(256)
conv_shift(const float* __restrict__ inp,
           const unsigned* __restrict__ Ahi, const unsigned* __restrict__ Alo,
           const float* __restrict__ e_b, const float* __restrict__ e_s,
           const float* __restrict__ e_o, float* __restrict__ out, int Oact) {
    extern __shared__ uint2 csm2[];      // [2][3456] (hi, lo) pairs

    const int b = blockIdx.y;
    const int tile = blockIdx.x;
    const int tid = threadIdx.x;
    const int warp = tid >> 5;
    const int lane = tid & 31;
    const int mt = warp >> 1;
    const int nh = warp & 1;

    float acc[4][4];
#pragma unroll
    for (int nt = 0; nt < 4; nt++)
#pragma unroll
        for (int r = 0; r < 4; r++) acc[nt][r] = 0.0f;

    const float* xb = inp + (size_t)b * 64 * HW;

    auto fill = [&](int slab, int buf) {
        uint2* bA = csm2 + buf * 3456;
        for (int e = tid; e < 3168; e += 256) {
            int r = e / 1056;
            int rem = e - r * 1056;
            int cp = rem / 66;
            int col = rem - cp * 66;
            int yy = tile - 1 + r;
            int px = col - 1;
            bool ok = ((unsigned)yy < 64u) && ((unsigned)px < 64u);
            const float* p0 = xb + (size_t)(slab * 32 + cp * 2) * HW + yy * 64 + px;
            float v0 = ok ? __ldg(p0) : 0.0f;
            float v1 = ok ? __ldg(p0 + HW) : 0.0f;
            __half h0 = __float2half(v0), h1 = __float2half(v1);
            __half l0 = __float2half(v0 - __half2float(h0));
            __half l1 = __float2half(v1 - __half2float(h1));
            bA[(r * 16 + cp) * 72 + col] = make_uint2(pack_h2(h0, h1), pack_h2(l0, l1));
        }
    };

    fill(0, 0);
    __syncthreads();

    for (int slab = 0; slab < 2; slab++) {
        if (slab == 0) fill(1, 1);
        const uint2* sb = csm2 + slab * 3456;
#pragma unroll
        for (int t = 0; t < 9; t++) {
            const int dy = t / 3, dx = t % 3;
            const uint2* rb = sb + dy * 16 * 72;
#pragma unroll
            for (int kcl = 0; kcl < 2; kcl++) {
                int kcg = (slab * 9 + t) * 2 + kcl;
                uint4 Ah = __ldg((const uint4*)(Ahi + (((size_t)kcg * 4 + mt) * 32 + lane) * 4));
                uint4 Al = __ldg((const uint4*)(Alo + (((size_t)kcg * 4 + mt) * 32 + lane) * 4));
                int boff = (kcl * 8 + (lane & 3)) * 72 + (lane >> 2) + nh * 32 + dx;
                const uint2* bp = rb + boff;
#pragma unroll
                for (int nt = 0; nt < 4; nt++) {
                    uint2 u0 = bp[nt * 8];            // (b0h, b0l)
                    uint2 u1 = bp[nt * 8 + 4 * 72];   // (b1h, b1l)
                    mma_f16(acc[nt], Ah.x, Ah.y, Ah.z, Ah.w, u0.x, u1.x);
                    mma_f16(acc[nt], Ah.x, Ah.y, Ah.z, Ah.w, u0.y, u1.y);
                    mma_f16(acc[nt], Al.x, Al.y, Al.z, Al.w, u0.x, u1.x);
                }
            }
        }
        __syncthreads();
    }

    int o = mt * 16 + (lane >> 2);
    float b0 = 0, s0 = 1, f0 = 0, b1 = 0, s1 = 1, f1 = 0;
    if (EPI == 1) {
        if (o < Oact)     { b0 = __ldg(e_b + o);     s0 = __ldg(e_s + o);     f0 = __ldg(e_o + o); }
        if (o + 8 < Oact) { b1 = __ldg(e_b + o + 8); s1 = __ldg(e_s + o + 8); f1 = __ldg(e_o + o + 8); }
    } else if (EPI == 2) {
        if (o < Oact)     b0 = __ldg(e_b + o);
        if (o + 8 < Oact) b1 = __ldg(e_b + o + 8);
    }
    int colb = tile * 64 + nh * 32 + (lane & 3) * 2;
    float* o0 = out + ((size_t)b * Oact + o) * HW + colb;
    float* o1 = o0 + 8 * HW;
#pragma unroll
    for (int nt = 0; nt < 4; nt++) {
        float v0a = acc[nt][0], v0b = acc[nt][1];
        float v1a = acc[nt][2], v1b = acc[nt][3];
        if (EPI == 1) {
            v0a = fmaxf((v0a + b0) * s0 + f0, 0.0f);
            v0b = fmaxf((v0b + b0) * s0 + f0, 0.0f);
            v1a = fmaxf((v1a + b1) * s1 + f1, 0.0f);
            v1b = fmaxf((v1b + b1) * s1 + f1, 0.0f);
        } else if (EPI == 2) {
            v0a += b0; v0b += b0; v1a += b1; v1b += b1;
        }
        if (o < Oact)
            *reinterpret_cast<float2*>(o0 + nt * 8) = make_float2(v0a, v0b);
        if (o + 8 < Oact)
            *reinterpret_cast<float2*>(o1 + nt * 8) = make_float2(v1a, v1b);
    }
}

// ---------------- deform table build: 1 int + 1 float4 -------------------------------
template <bool MASKED>
__device__ __forceinline__ void build_tables(
    int tid, int tile, int b, const float* __restrict__ offs, int offBS,
    const float* __restrict__ msk, int* s_ii, float4* s_ww) {
    for (int e = tid; e < 576; e += 256) {
        int k = e >> 6, p = e & 63;
        int pix = tile * 64 + p;
        float py = (float)(tile - 1 + k / 3)
                 + offs[(size_t)b * offBS + (2 * k) * HW + pix];
        float px = (float)(p - 1 + k % 3)
                 + offs[(size_t)b * offBS + (2 * k + 1) * HW + pix];
        float m = MASKED ? msk[(size_t)b * 9 * HW + k * HW + pix] : 1.0f;
        float fy = floorf(py), fx = floorf(px);
        int iy = (int)fy, ix = (int)fx;
        float ay = py - fy, ax = px - fx;
        bool vy0 = (iy >= 0) && (iy < 64);
        bool vy1 = (iy >= -1) && (iy < 63);
        bool vx0 = (ix >= 0) && (ix < 64);
        bool vx1 = (ix >= -1) && (ix < 63);
        int yb = min(max(iy, 0), 62), xb = min(max(ix, 0), 62);
        float wAx = 0.0f, wBx = 0.0f;
        if (vx0) { if (min(max(ix, 0), 63) == xb) wAx += 1.0f - ax; else wBx += 1.0f - ax; }
        if (vx1) { if (min(max(ix + 1, 0), 63) == xb) wAx += ax; else wBx += ax; }
        float wy0 = 0.0f, wy1 = 0.0f;
        if (vy0) { if (min(max(iy, 0), 63) == yb) wy0 += 1.0f - ay; else wy1 += 1.0f - ay; }
        if (vy1) { if (min(max(iy + 1, 0), 63) == yb) wy0 += ay; else wy1 += ay; }
        wy0 *= m; wy1 *= m;
        s_ii[e] = yb * 64 + xb;
        s_ww[e] = make_float4(wy0 * wAx, wy0 * wBx, wy1 * wAx, wy1 * wBx);
    }
}

// ---------------- DCNv1 mid conv: interleaved-pair quad gather -----------------------
__global__ void __launch_bounds__(256)
dcn_mid(const uint4* __restrict__ hq,
        const unsigned* __restrict__ Ahi, const unsigned* __restrict__ Alo,
        const float* __restrict__ offs, int offBS, float* __restrict__ out) {
    extern __shared__ unsigned msm[];
    unsigned* s_bhA = msm;               // [2][2304]
    unsigned* s_blA = msm + 2 * 2304;    // [2][2304]
    __shared__ int s_ii[576];
    __shared__ float4 s_ww[576];

    const int b = blockIdx.y;
    const int tile = blockIdx.x;
    const int tid = threadIdx.x;
    const int warp = tid >> 5;
    const int lane = tid & 31;
    const int mt = warp >> 1;
    const int nh = warp & 1;
    const int q = lane >> 2;

    build_tables<false>(tid, tile, b, offs, offBS, nullptr, s_ii, s_ww);
    __syncthreads();

    float acc[4][4];
#pragma unroll
    for (int nt = 0; nt < 4; nt++)
#pragma unroll
        for (int r = 0; r < 4; r++) acc[nt][r] = 0.0f;

    const int p = tid & 63;
    const int jp0 = tid >> 6;
    const int perm = (p & 7) * 8 + (p >> 3);

    auto gather = [&](int slab, int buf) {
        unsigned* bh = s_bhA + buf * 2304;
        unsigned* bl = s_blA + buf * 2304;
        int r = slab * 64 + p;              // slab == tap
        int ib = s_ii[r];
        float4 w4 = s_ww[r];
        const uint4* xc = hq + ((size_t)b * 32 + jp0) * HW;   // channel pair c2 = jp0
        int jp = jp0;
#pragma unroll
        for (int i = 0; i < 8; i++) {
            uint4 Q = __ldg(xc + ib);
            float va = dot2h(w4, Q.x, Q.y);
            float vb = dot2h(w4, Q.z, Q.w);
            __half vah = __float2half(va), vbh = __float2half(vb);
            __half val = __float2half(va - __half2float(vah));
            __half vbl = __float2half(vb - __half2float(vbh));
            bh[jp * 72 + perm] = pack_h2(vah, vbh);
            bl[jp * 72 + perm] = pack_h2(val, vbl);
            jp += 4;
            xc += 4 * HW;    // advance 4 channel pairs = 8 channels
        }
    };

    gather(0, 0);
    __syncthreads();

    for (int slab = 0; slab < 9; slab++) {
        if (slab < 8) gather(slab + 1, (slab + 1) & 1);
        const unsigned* sbh = s_bhA + (slab & 1) * 2304;
        const unsigned* sbl = s_blA + (slab & 1) * 2304;
#pragma unroll
        for (int kc = 0; kc < 4; kc++) {
            int kcg = slab * 4 + kc;
            uint4 Ah = __ldg((const uint4*)(Ahi + (((size_t)kcg * 4 + mt) * 32 + lane) * 4));
            uint4 Al = __ldg((const uint4*)(Alo + (((size_t)kcg * 4 + mt) * 32 + lane) * 4));
            int boff = (kc * 8 + (lane & 3)) * 72 + q * 8 + nh * 4;
            uint4 B0h = *(const uint4*)(sbh + boff);
            uint4 B1h = *(const uint4*)(sbh + boff + 4 * 72);
            uint4 B0l = *(const uint4*)(sbl + boff);
            uint4 B1l = *(const uint4*)(sbl + boff + 4 * 72);
            mma_f16(acc[0], Ah.x, Ah.y, Ah.z, Ah.w, B0h.x, B1h.x);
            mma_f16(acc[0], Ah.x, Ah.y, Ah.z, Ah.w, B0l.x, B1l.x);
            mma_f16(acc[0], Al.x, Al.y, Al.z, Al.w, B0h.x, B1h.x);
            mma_f16(acc[1], Ah.x, Ah.y, Ah.z, Ah.w, B0h.y, B1h.y);
            mma_f16(acc[1], Ah.x, Ah.y, Ah.z, Ah.w, B0l.y, B1l.y);
            mma_f16(acc[1], Al.x, Al.y, Al.z, Al.w, B0h.y, B1h.y);
            mma_f16(acc[2], Ah.x, Ah.y, Ah.z, Ah.w, B0h.z, B1h.z);
            mma_f16(acc[2], Ah.x, Ah.y, Ah.z, Ah.w, B0l.z, B1l.z);
            mma_f16(acc[2], Al.x, Al.y, Al.z, Al.w, B0h.z, B1h.z);
            mma_f16(acc[3], Ah.x, Ah.y, Ah.z, Ah.w, B0h.w, B1h.w);
            mma_f16(acc[3], Ah.x, Ah.y, Ah.z, Ah.w, B0l.w, B1l.w);
            mma_f16(acc[3], Al.x, Al.y, Al.z, Al.w, B0h.w, B1h.w);
        }
        __syncthreads();
    }

    int o = mt * 16 + (lane >> 2);
    int colb = tile * 64 + nh * 32 + (lane & 3) * 2;
    float* o0 = out + ((size_t)b * 64 + o) * HW + colb;
    float* o1 = o0 + 8 * HW;
#pragma unroll
    for (int nt = 0; nt < 4; nt++) {
        *reinterpret_cast<float2*>(o0 + nt * 8) = make_float2(acc[nt][0], acc[nt][1]);
        *reinterpret_cast<float2*>(o1 + nt * 8) = make_float2(acc[nt][2], acc[nt][3]);
    }
}

// ---------------- final modulated DCNv2: interleaved-pair quad gather ----------------
__global__ void __launch_bounds__(256)
dcn_final_f16(const uint4* __restrict__ xq, const unsigned* __restrict__ Af,
              const float* __restrict__ offs, const float* __restrict__ msk,
              const float* __restrict__ bias, float* __restrict__ out) {
    __shared__ unsigned s_bA[2][32 * 72];
    __shared__ int s_ii[576];
    __shared__ float4 s_ww[576];

    const int b = blockIdx.y;
    const int tile = blockIdx.x;
    const int tid = threadIdx.x;
    const int warp = tid >> 5;
    const int lane = tid & 31;
    const int q = lane >> 2;

    build_tables<true>(tid, tile, b, offs, 36 * HW, msk, s_ii, s_ww);
    __syncthreads();

    float acc[2][8][4];
#pragma unroll
    for (int mtl = 0; mtl < 2; mtl++)
#pragma unroll
        for (int nt = 0; nt < 8; nt++)
#pragma unroll
            for (int r = 0; r < 4; r++) acc[mtl][nt][r] = 0.0f;

    const int p = tid & 63;
    const int jp0 = tid >> 6;
    const int perm = (p & 7) * 8 + (p >> 3);

    auto gather = [&](int slab, int buf) {
        unsigned* bdst = s_bA[buf];
        int kk = slab >> 2;
        int r = kk * 64 + p;
        int ib = s_ii[r];
        float4 w4 = s_ww[r];
        // channel pair c2 = (slab&3)*32 + jp0
        const uint4* xc = xq + ((size_t)b * 128 + (slab & 3) * 32 + jp0) * HW;
        int jp = jp0;
#pragma unroll
        for (int i = 0; i < 8; i++) {
            uint4 Q = __ldg(xc + ib);
            float va = dot2h(w4, Q.x, Q.y);
            float vb = dot2h(w4, Q.z, Q.w);
            bdst[jp * 72 + perm] = pack_h2(__float2half(va), __float2half(vb));
            jp += 4;
            xc += 4 * HW;
        }
    };

    gather(0, 0);
    __syncthreads();

    for (int slab = 0; slab < 36; slab++) {
        if (slab < 35) gather(slab + 1, (slab + 1) & 1);
        const unsigned* sb = s_bA[slab & 1];
#pragma unroll
        for (int kc = 0; kc < 4; kc++) {
            int kcg = slab * 4 + kc;
            const unsigned* ap = Af + (((size_t)kcg * 16 + warp * 2) * 32 + lane) * 4;
            uint4 A0 = __ldg((const uint4*)ap);
            uint4 A1 = __ldg((const uint4*)(ap + 128));

            int boff = (kc * 8 + (lane & 3)) * 72 + q * 8;
            uint4 B0a = *(const uint4*)(sb + boff);
            uint4 B0b = *(const uint4*)(sb + boff + 4);
            uint4 B1a = *(const uint4*)(sb + boff + 4 * 72);
            uint4 B1b = *(const uint4*)(sb + boff + 4 * 72 + 4);
            mma_f16(acc[0][0], A0.x, A0.y, A0.z, A0.w, B0a.x, B1a.x);
            mma_f16(acc[1][0], A1.x, A1.y, A1.z, A1.w, B0a.x, B1a.x);
            mma_f16(acc[0][1], A0.x, A0.y, A0.z, A0.w, B0a.y, B1a.y);
            mma_f16(acc[1][1], A1.x, A1.y, A1.z, A1.w, B0a.y, B1a.y);
            mma_f16(acc[0][2], A0.x, A0.y, A0.z, A0.w, B0a.z, B1a.z);
            mma_f16(acc[1][2], A1.x, A1.y, A1.z, A1.w, B0a.z, B1a.z);
            mma_f16(acc[0][3], A0.x, A0.y, A0.z, A0.w, B0a.w, B1a.w);
            mma_f16(acc[1][3], A1.x, A1.y, A1.z, A1.w, B0a.w, B1a.w);
            mma_f16(acc[0][4], A0.x, A0.y, A0.z, A0.w, B0b.x, B1b.x);
            mma_f16(acc[1][4], A1.x, A1.y, A1.z, A1.w, B0b.x, B1b.x);
            mma_f16(acc[0][5], A0.x, A0.y, A0.z, A0.w, B0b.y, B1b.y);
            mma_f16(acc[1][5], A1.x, A1.y, A1.z, A1.w, B0b.y, B1b.y);
            mma_f16(acc[0][6], A0.x, A0.y, A0.z, A0.w, B0b.z, B1b.z);
            mma_f16(acc[1][6], A1.x, A1.y, A1.z, A1.w, B0b.z, B1b.z);
            mma_f16(acc[0][7], A0.x, A0.y, A0.z, A0.w, B0b.w, B1b.w);
            mma_f16(acc[1][7], A1.x, A1.y, A1.z, A1.w, B0b.w, B1b.w);
        }
        __syncthreads();
    }

#pragma unroll
    for (int mtl = 0; mtl < 2; mtl++) {
        int o = warp * 32 + mtl * 16 + (lane >> 2);
        float b_lo = __ldg(bias + o);
        float b_hi = __ldg(bias + o + 8);
        float* o0 = out + ((size_t)b * 256 + o) * HW + tile * 64 + (lane & 3) * 2;
        float* o1 = o0 + 8 * HW;
#pragma unroll
        for (int nt = 0; nt < 8; nt++) {
            *reinterpret_cast<float2*>(o0 + nt * 8) =
                make_float2(acc[mtl][nt][0] + b_lo, acc[mtl][nt][1] + b_lo);
            *reinterpret_cast<float2*>(o1 + nt * 8) =
                make_float2(acc[mtl][nt][2] + b_hi, acc[mtl][nt][3] + b_hi);
        }
    }
}

// ---------------- host launcher ------------------------------------------------------
extern "C" void kernel_launch(void* const* d_in, const int* in_sizes, int n_in,
                              void* d_out, int out_size) {
    const float* x       = (const float*)d_in[0];
    const float* S       = (const float*)d_in[1];
    const float* sp_w1   = (const float*)d_in[2];
    const float* sp_b1   = (const float*)d_in[3];
    const float* sp_s1   = (const float*)d_in[4];
    const float* sp_o1   = (const float*)d_in[5];
    const float* sp_w2   = (const float*)d_in[6];
    const float* sp_b2   = (const float*)d_in[7];
    const float* sp_s2   = (const float*)d_in[8];
    const float* sp_o2   = (const float*)d_in[9];
    const float* sp_w3   = (const float*)d_in[10];
    const float* sp_b3   = (const float*)d_in[11];
    const float* sp_s3   = (const float*)d_in[12];
    const float* sp_o3   = (const float*)d_in[13];
    const float* off_w   = (const float*)d_in[14];
    const float* off_b   = (const float*)d_in[15];
    const float* dcoff_w = (const float*)d_in[16];
    const float* dcoff_b = (const float*)d_in[17];
    const float* dc_w    = (const float*)d_in[18];
    const float* m_w     = (const float*)d_in[19];
    const float* m_b     = (const float*)d_in[20];
    const float* weight  = (const float*)d_in[21];
    const float* bias    = (const float*)d_in[22];

    float *h1, *h2, *h3, *feat, *off, *mask, *b36;
    uint4 *xqi, *hqi3;
    unsigned *Af, *Ah2, *Al2, *Ah3, *Al3, *Ahdc, *Aldc, *Ah36, *Al36;
    cudaGetSymbolAddress((void**)&h1,   g_h1);
    cudaGetSymbolAddress((void**)&h2,   g_h2);
    cudaGetSymbolAddress((void**)&h3,   g_h3);
    cudaGetSymbolAddress((void**)&feat, g_feat);
    cudaGetSymbolAddress((void**)&off,  g_off);
    cudaGetSymbolAddress((void**)&mask, g_mask);
    cudaGetSymbolAddress((void**)&b36,  g_b36);
    cudaGetSymbolAddress((void**)&xqi,  g_xqi);
    cudaGetSymbolAddress((void**)&hqi3, g_hqi3);
    cudaGetSymbolAddress((void**)&Af,   g_Af);
    cudaGetSymbolAddress((void**)&Ah2,  g_Ah2);
    cudaGetSymbolAddress((void**)&Al2,  g_Al2);
    cudaGetSymbolAddress((void**)&Ah3,  g_Ah3);
    cudaGetSymbolAddress((void**)&Al3,  g_Al3);
    cudaGetSymbolAddress((void**)&Ahdc, g_Ahdc);
    cudaGetSymbolAddress((void**)&Aldc, g_Aldc);
    cudaGetSymbolAddress((void**)&Ah36, g_Ah36);
    cudaGetSymbolAddress((void**)&Al36, g_Al36);

    const int SMEM_SHIFT = 2 * 3456 * 8;   // 55296 (uint2 pairs)
    const int SMEM_MID   = 4 * 2304 * 4;   // 36864
    cudaFuncSetAttribute(conv_shift<1>,
                         cudaFuncAttributeMaxDynamicSharedMemorySize, SMEM_SHIFT);
    cudaFuncSetAttribute(conv_shift<2>,
                         cudaFuncAttributeMaxDynamicSharedMemorySize, SMEM_SHIFT);
    cudaFuncSetAttribute(dcn_mid,
                         cudaFuncAttributeMaxDynamicSharedMemorySize, SMEM_MID);

    auto tgrid = [](int n) { return (n + 255) / 256; };
    dim3 grid(64, BATCH);

    prep_shift_f16<<<tgrid(64 * 576), 256>>>(sp_w2, Ah2, Al2, 64);                // 0
    prep_shift_f16<<<tgrid(64 * 576), 256>>>(sp_w3, Ah3, Al3, 64);                // 1
    sp1_kernel<<<grid, 256>>>(S, sp_w1, sp_b1, sp_s1, sp_o1, h1);                 // 2
    conv_shift<1><<<grid, 256, SMEM_SHIFT>>>(h1, Ah2, Al2,
                                             sp_b2, sp_s2, sp_o2, h2, 64);        // 3 <- ncu
    conv_shift<1><<<grid, 256, SMEM_SHIFT>>>(h2, Ah3, Al3,
                                             sp_b3, sp_s3, sp_o3, h3, 64);        // 4
    quad_h2i<<<tgrid(BATCH * 128 * HW), 256>>>(x, xqi, BATCH * 128 * HW, 128);    // 5
    prep_shift_w36<<<tgrid(64 * 576), 256>>>(off_w, dcoff_w, Ah36, Al36);         // 6
    concat_bias36<<<1, 36>>>(off_b, dcoff_b, b36);                                // 7
    prep_middc_tap<<<tgrid(64 * 576), 256>>>(dc_w, Ahdc, Aldc);                   // 8
    conv_shift<2><<<grid, 256, SMEM_SHIFT>>>(h3, Ah36, Al36,
                                             b36, nullptr, nullptr, off, 36);     // 9
    quad_h2i<<<tgrid(BATCH * 32 * HW), 256>>>(h3, hqi3, BATCH * 32 * HW, 32);     // 10
    dcn_mid<<<grid, 256, SMEM_MID>>>(hqi3, Ahdc, Aldc, off + 18 * HW, 36 * HW, feat); // 11
    mask_kernel<<<(BATCH * HW + 255) / 256, 256>>>(feat, m_w, m_b, mask);         // 12
    prep_final_f16<<<tgrid(256 * 2304), 256>>>(weight, Af);                       // 13
    dcn_final_f16<<<grid, 256>>>(xqi, Af, off, mask, bias, (float*)d_out);        // 14
}

// round 14
// speedup vs baseline: 1.0628x; 1.0628x over previous
#include <cuda_runtime.h>
#include <cuda_fp16.h>
#include <math.h>
#include <stdint.h>

#define HW 4096     // 64*64
#define BATCH 8

// ---------------- scratch (static device globals; no allocation) ----------------
__device__ float g_h1  [BATCH*64*HW];
__device__ float g_h2  [BATCH*64*HW];
__device__ float g_h3  [BATCH*64*HW];
__device__ float g_feat[BATCH*64*HW];
__device__ float g_off [BATCH*36*HW];   // ch 0..17 = offset, 18..35 = dc_off
__device__ float g_mask[BATCH*9*HW];
__device__ float g_b36 [36];

// channel-pair-interleaved f16 quads:
// q[(b*C/2 + c2)*HW + pix] = uint4{ pack(c0:x,x+1), pack(c0:y+1 row), pack(c1:...), pack(c1:...) }
__device__ uint4 g_xqi [BATCH*128*HW];  // 64MB (x, 256 ch -> 128 pairs)
__device__ uint4 g_hqi3[BATCH*32*HW];   // 16MB (h3, 64 ch -> 32 pairs)

// f16 fragment-packed weights (each u32 = 2 f16 along K)
__device__ unsigned g_Af[144*16*32*4];
#define MIDA (36*4*32*4)
__device__ unsigned g_Ah2 [MIDA], g_Al2 [MIDA];   // shift-order
__device__ unsigned g_Ah3 [MIDA], g_Al3 [MIDA];   // shift-order
__device__ unsigned g_Ah36[MIDA], g_Al36[MIDA];   // shift-order
__device__ unsigned g_Ahdc[MIDA], g_Aldc[MIDA];   // tap-major (K=kk*64+c)

// ---------------- helpers ------------------------------------------------------------
__device__ __forceinline__ void mma_f16(float* acc, unsigned a0, unsigned a1,
                                        unsigned a2, unsigned a3,
                                        unsigned b0, unsigned b1) {
    asm volatile(
        "mma.sync.aligned.m16n8k16.row.col.f32.f16.f16.f32 "
        "{%0,%1,%2,%3}, {%4,%5,%6,%7}, {%8,%9}, {%0,%1,%2,%3};"
        : "+f"(acc[0]), "+f"(acc[1]), "+f"(acc[2]), "+f"(acc[3])
        : "r"(a0), "r"(a1), "r"(a2), "r"(a3), "r"(b0), "r"(b1));
}

__device__ __forceinline__ void frag_coords(int om, int kk, int& lane, int& reg, int& half) {
    int kpair = kk >> 1;
    half = kk & 1;
    lane = (om & 7) * 4 + (kpair & 3);
    reg = (om >> 3) + ((kpair >> 2) << 1);
}

__device__ __forceinline__ unsigned pack_h2(__half lo, __half hi) {
    return (unsigned)__half_as_ushort(lo) | ((unsigned)__half_as_ushort(hi) << 16);
}

__device__ __forceinline__ float dot2h(float4 w, unsigned qa, unsigned qb) {
    float2 f0 = __half22float2(*reinterpret_cast<__half2*>(&qa));
    float2 f1 = __half22float2(*reinterpret_cast<__half2*>(&qb));
    return w.x * f0.x + w.y * f0.y + w.z * f1.x + w.w * f1.y;
}

// ---------------- weight prep kernels -------------------------------------------------
__global__ void prep_middc_tap(const float* __restrict__ w, unsigned* __restrict__ hi,
                               unsigned* __restrict__ lo) {
    int i = blockIdx.x * blockDim.x + threadIdx.x;
    if (i >= 64 * 576) return;
    int K = i % 576;
    int o = i / 576;
    float v = w[o * 576 + K];
    __half vh = __float2half(v);
    __half vl = __float2half(v - __half2float(vh));
    int c = K / 9, kk = K - c * 9;
    int Kn = kk * 64 + c;
    int kc = Kn >> 4, kwi = Kn & 15;
    int lane, reg, half;
    frag_coords(o & 15, kwi, lane, reg, half);
    size_t base = ((((size_t)kc * 4 + (o >> 4)) * 32 + lane) * 4 + reg) * 2 + half;
    ((__half*)hi)[base] = vh;
    ((__half*)lo)[base] = vl;
}

__global__ void prep_shift_f16(const float* __restrict__ w, unsigned* __restrict__ hi,
                               unsigned* __restrict__ lo, int O) {
    int i = blockIdx.x * blockDim.x + threadIdx.x;
    if (i >= 64 * 576) return;
    int K = i % 576;
    int o = i / 576;
    float v = (o < O) ? w[o * 576 + K] : 0.0f;
    __half vh = __float2half(v);
    __half vl = __float2half(v - __half2float(vh));
    int c = K / 9, kk = K % 9;
    int slab = c >> 5, cl = c & 31;
    int kcg = (slab * 9 + kk) * 2 + (cl >> 4);
    int lane, reg, half;
    frag_coords(o & 15, cl & 15, lane, reg, half);
    size_t base = ((((size_t)kcg * 4 + (o >> 4)) * 32 + lane) * 4 + reg) * 2 + half;
    ((__half*)hi)[base] = vh;
    ((__half*)lo)[base] = vl;
}

__global__ void prep_shift_w36(const float* __restrict__ wa, const float* __restrict__ wb,
                               unsigned* __restrict__ hi, unsigned* __restrict__ lo) {
    int i = blockIdx.x * blockDim.x + threadIdx.x;
    if (i >= 64 * 576) return;
    int K = i % 576;
    int o = i / 576;
    float v = 0.0f;
    if (o < 18) v = wa[o * 576 + K];
    else if (o < 36) v = wb[(o - 18) * 576 + K];
    __half vh = __float2half(v);
    __half vl = __float2half(v - __half2float(vh));
    int c = K / 9, kk = K % 9;
    int slab = c >> 5, cl = c & 31;
    int kcg = (slab * 9 + kk) * 2 + (cl >> 4);
    int lane, reg, half;
    frag_coords(o & 15, cl & 15, lane, reg, half);
    size_t base = ((((size_t)kcg * 4 + (o >> 4)) * 32 + lane) * 4 + reg) * 2 + half;
    ((__half*)hi)[base] = vh;
    ((__half*)lo)[base] = vl;
}

// final: tap-major Kn = kk*256 + c
__global__ void prep_final_f16(const float* __restrict__ w, unsigned* __restrict__ dst) {
    int i = blockIdx.x * blockDim.x + threadIdx.x;
    if (i >= 256 * 2304) return;
    int K = i % 2304;
    int o = i / 2304;
    int c = K / 9, kk = K - c * 9;
    int Kn = kk * 256 + c;
    int kc = Kn >> 4, kwi = Kn & 15;
    int lane, reg, half;
    frag_coords(o & 15, kwi, lane, reg, half);
    size_t base = ((((size_t)kc * 16 + (o >> 4)) * 32 + lane) * 4 + reg) * 2 + half;
    ((__half*)dst)[base] = __float2half(w[i]);
}

__global__ void concat_bias36(const float* __restrict__ a, const float* __restrict__ b,
                              float* __restrict__ dst) {
    int i = threadIdx.x;
    if (i < 18) dst[i] = a[i];
    else if (i < 36) dst[i] = b[i - 18];
}

// ---------------- channel-pair interleaved f16 quad shingle ---------------------------
__global__ void quad_h2i(const float* __restrict__ src, uint4* __restrict__ dst,
                         int total, int C2) {
    int i = blockIdx.x * blockDim.x + threadIdx.x;
    if (i >= total) return;
    int pix = i & (HW - 1);
    int bc2 = i >> 12;
    int b = bc2 / C2;
    int c2 = bc2 - b * C2;
    int xx = pix & 63, yy = pix >> 6;
    const float* s0 = src + ((size_t)(b * 2 * C2 + c2 * 2)) * HW;
    const float* s1 = s0 + HW;
    bool okx = (xx < 63), oky = (yy < 63);
    float A0 = s0[pix];
    float B0 = okx ? s0[pix + 1] : 0.0f;
    float C0 = oky ? s0[pix + 64] : 0.0f;
    float D0 = (okx && oky) ? s0[pix + 65] : 0.0f;
    float A1 = s1[pix];
    float B1 = okx ? s1[pix + 1] : 0.0f;
    float C1 = oky ? s1[pix + 64] : 0.0f;
    float D1 = (okx && oky) ? s1[pix + 65] : 0.0f;
    dst[i] = make_uint4(pack_h2(__float2half(A0), __float2half(B0)),
                        pack_h2(__float2half(C0), __float2half(D0)),
                        pack_h2(__float2half(A1), __float2half(B1)),
                        pack_h2(__float2half(C1), __float2half(D1)));
}

// ---------------- 1x1 conv + sigmoid -------------------------------------------------
__global__ void mask_kernel(const float* __restrict__ feat, const float* __restrict__ mw,
                            const float* __restrict__ mb, float* __restrict__ mask) {
    int i = blockIdx.x * blockDim.x + threadIdx.x;
    if (i >= BATCH * HW) return;
    int b = i >> 12;
    int pix = i & (HW - 1);
    float acc[9];
#pragma unroll
    for (int o = 0; o < 9; o++) acc[o] = __ldg(mb + o);
    const float* fp = feat + (size_t)b * 64 * HW + pix;
    for (int c = 0; c < 64; c++) {
        float v = __ldg(fp + c * HW);
#pragma unroll
        for (int o = 0; o < 9; o++) acc[o] += v * __ldg(mw + o * 64 + c);
    }
#pragma unroll
    for (int o = 0; o < 9; o++)
        mask[((size_t)b * 9 + o) * HW + pix] = 1.0f / (1.0f + expf(-acc[o]));
}

// ---------------- sp1: fused resize + conv3x3 (CIN=3) + BN + ReLU, fp32 --------------
__device__ __forceinline__ float resize_at(const float* __restrict__ p, int y, int x) {
    const float scale = 127.0f / 63.0f;
    float ys = y * scale, xs = x * scale;
    float fy = floorf(ys), fx = floorf(xs);
    int y0 = (int)fy, x0 = (int)fx;
    int y1 = min(y0 + 1, 127), x1 = min(x0 + 1, 127);
    float wy = ys - fy, wx = xs - fx;
    return p[y0 * 128 + x0] * (1.0f - wy) * (1.0f - wx)
         + p[y0 * 128 + x1] * (1.0f - wy) * wx
         + p[y1 * 128 + x0] * wy * (1.0f - wx)
         + p[y1 * 128 + x1] * wy * wx;
}

__global__ void __launch_bounds__(256)
sp1_kernel(const float* __restrict__ S, const float* __restrict__ w1,
           const float* __restrict__ e_b, const float* __restrict__ e_s,
           const float* __restrict__ e_o, float* __restrict__ out) {
    __shared__ __align__(16) float s_t[576];
    const int b = blockIdx.y;
    const int tile = blockIdx.x;
    const int tid = threadIdx.x;
    const int o = tid & 63;
    const int pbase = (tid >> 6) * 16;

    float acc[16];
#pragma unroll
    for (int j = 0; j < 16; j++) acc[j] = 0.0f;

    for (int c = 0; c < 3; c++) {
        const float* Sc = S + (size_t)(b * 3 + c) * 128 * 128;
        for (int e = tid; e < 576; e += 256) {
            int k = e >> 6, p = e & 63;
            int yy = tile + k / 3 - 1;
            int xx = p + k % 3 - 1;
            s_t[e] = ((unsigned)yy < 64u && (unsigned)xx < 64u)
                         ? resize_at(Sc, yy, xx) : 0.0f;
        }
        __syncthreads();

        float wv[9];
#pragma unroll
        for (int k = 0; k < 9; k++) wv[k] = __ldg(w1 + o * 27 + c * 9 + k);

#pragma unroll
        for (int k = 0; k < 9; k++) {
            const float4* sp = reinterpret_cast<const float4*>(s_t + k * 64 + pbase);
#pragma unroll
            for (int j4 = 0; j4 < 4; j4++) {
                float4 sv = sp[j4];
                acc[j4 * 4 + 0] += wv[k] * sv.x;
                acc[j4 * 4 + 1] += wv[k] * sv.y;
                acc[j4 * 4 + 2] += wv[k] * sv.z;
                acc[j4 * 4 + 3] += wv[k] * sv.w;
            }
        }
        __syncthreads();
    }

    float bb = __ldg(e_b + o), ssc = __ldg(e_s + o), oof = __ldg(e_o + o);
    float* op = out + ((size_t)b * 64 + o) * HW + tile * 64 + pbase;
#pragma unroll
    for (int j = 0; j < 16; j++)
        op[j] = fmaxf((acc[j] + bb) * ssc + oof, 0.0f);
}

// ---------------- plain conv3x3 via shifted-window mma (R12 version) -----------------
template <int EPI>
__global__ void __launch_bounds__(256)
conv_shift(const float* __restrict__ inp,
           const unsigned* __restrict__ Ahi, const unsigned* __restrict__ Alo,
           const float* __restrict__ e_b, const float* __restrict__ e_s,
           const float* __restrict__ e_o, float* __restrict__ out, int Oact) {
    extern __shared__ unsigned csm[];
    unsigned* s_bhA = csm;              // [2][3456]
    unsigned* s_blA = csm + 2 * 3456;   // [2][3456]

    const int b = blockIdx.y;
    const int tile = blockIdx.x;
    const int tid = threadIdx.x;
    const int warp = tid >> 5;
    const int lane = tid & 31;
    const int mt = warp >> 1;
    const int nh = warp & 1;

    float acc[4][4];
#pragma unroll
    for (int nt = 0; nt < 4; nt++)
#pragma unroll
        for (int r = 0; r < 4; r++) acc[nt][r] = 0.0f;

    const float* xb = inp + (size_t)b * 64 * HW;

    auto fill = [&](int slab, int buf) {
        unsigned* bh = s_bhA + buf * 3456;
        unsigned* bl = s_blA + buf * 3456;
        for (int e = tid; e < 3168; e += 256) {
            int r = e / 1056;
            int rem = e - r * 1056;
            int cp = rem / 66;
            int col = rem - cp * 66;
            int yy = tile - 1 + r;
            int px = col - 1;
            bool ok = ((unsigned)yy < 64u) && ((unsigned)px < 64u);
            const float* p0 = xb + (size_t)(slab * 32 + cp * 2) * HW + yy * 64 + px;
            float v0 = ok ? __ldg(p0) : 0.0f;
            float v1 = ok ? __ldg(p0 + HW) : 0.0f;
            __half h0 = __float2half(v0), h1 = __float2half(v1);
            __half l0 = __float2half(v0 - __half2float(h0));
            __half l1 = __float2half(v1 - __half2float(h1));
            int idx = (r * 16 + cp) * 72 + col;
            bh[idx] = pack_h2(h0, h1);
            bl[idx] = pack_h2(l0, l1);
        }
    };

    fill(0, 0);
    __syncthreads();

    for (int slab = 0; slab < 2; slab++) {
        if (slab == 0) fill(1, 1);
        const unsigned* sbh = s_bhA + slab * 3456;
        const unsigned* sbl = s_blA + slab * 3456;
#pragma unroll
        for (int t = 0; t < 9; t++) {
            const int dy = t / 3, dx = t % 3;
            const unsigned* rbh = sbh + dy * 16 * 72;
            const unsigned* rbl = sbl + dy * 16 * 72;
#pragma unroll
            for (int kcl = 0; kcl < 2; kcl++) {
                int kcg = (slab * 9 + t) * 2 + kcl;
                uint4 Ah = __ldg((const uint4*)(Ahi + (((size_t)kcg * 4 + mt) * 32 + lane) * 4));
                uint4 Al = __ldg((const uint4*)(Alo + (((size_t)kcg * 4 + mt) * 32 + lane) * 4));
                int boff = (kcl * 8 + (lane & 3)) * 72 + (lane >> 2) + nh * 32 + dx;
                const unsigned* bh = rbh + boff;
                const unsigned* bl = rbl + boff;
#pragma unroll
                for (int nt = 0; nt < 4; nt++) {
                    unsigned b0h = bh[nt * 8], b1h = bh[nt * 8 + 4 * 72];
                    unsigned b0l = bl[nt * 8], b1l = bl[nt * 8 + 4 * 72];
                    mma_f16(acc[nt], Ah.x, Ah.y, Ah.z, Ah.w, b0h, b1h);
                    mma_f16(acc[nt], Ah.x, Ah.y, Ah.z, Ah.w, b0l, b1l);
                    mma_f16(acc[nt], Al.x, Al.y, Al.z, Al.w, b0h, b1h);
                }
            }
        }
        __syncthreads();
    }

    int o = mt * 16 + (lane >> 2);
    float b0 = 0, s0 = 1, f0 = 0, b1 = 0, s1 = 1, f1 = 0;
    if (EPI == 1) {
        if (o < Oact)     { b0 = __ldg(e_b + o);     s0 = __ldg(e_s + o);     f0 = __ldg(e_o + o); }
        if (o + 8 < Oact) { b1 = __ldg(e_b + o + 8); s1 = __ldg(e_s + o + 8); f1 = __ldg(e_o + o + 8); }
    } else if (EPI == 2) {
        if (o < Oact)     b0 = __ldg(e_b + o);
        if (o + 8 < Oact) b1 = __ldg(e_b + o + 8);
    }
    int colb = tile * 64 + nh * 32 + (lane & 3) * 2;
    float* o0 = out + ((size_t)b * Oact + o) * HW + colb;
    float* o1 = o0 + 8 * HW;
#pragma unroll
    for (int nt = 0; nt < 4; nt++) {
        float v0a = acc[nt][0], v0b = acc[nt][1];
        float v1a = acc[nt][2], v1b = acc[nt][3];
        if (EPI == 1) {
            v0a = fmaxf((v0a + b0) * s0 + f0, 0.0f);
            v0b = fmaxf((v0b + b0) * s0 + f0, 0.0f);
            v1a = fmaxf((v1a + b1) * s1 + f1, 0.0f);
            v1b = fmaxf((v1b + b1) * s1 + f1, 0.0f);
        } else if (EPI == 2) {
            v0a += b0; v0b += b0; v1a += b1; v1b += b1;
        }
        if (o < Oact)
            *reinterpret_cast<float2*>(o0 + nt * 8) = make_float2(v0a, v0b);
        if (o + 8 < Oact)
            *reinterpret_cast<float2*>(o1 + nt * 8) = make_float2(v1a, v1b);
    }
}

// ---------------- deform table build: 1 int + 1 float4 -------------------------------
template <bool MASKED>
__device__ __forceinline__ void build_tables(
    int tid, int tile, int b, const float* __restrict__ offs, int offBS,
    const float* __restrict__ msk, int* s_ii, float4* s_ww) {
    for (int e = tid; e < 576; e += 256) {
        int k = e >> 6, p = e & 63;
        int pix = tile * 64 + p;
        float py = (float)(tile - 1 + k / 3)
                 + offs[(size_t)b * offBS + (2 * k) * HW + pix];
        float px = (float)(p - 1 + k % 3)
                 + offs[(size_t)b * offBS + (2 * k + 1) * HW + pix];
        float m = MASKED ? msk[(size_t)b * 9 * HW + k * HW + pix] : 1.0f;
        float fy = floorf(py), fx = floorf(px);
        int iy = (int)fy, ix = (int)fx;
        float ay = py - fy, ax = px - fx;
        bool vy0 = (iy >= 0) && (iy < 64);
        bool vy1 = (iy >= -1) && (iy < 63);
        bool vx0 = (ix >= 0) && (ix < 64);
        bool vx1 = (ix >= -1) && (ix < 63);
        int yb = min(max(iy, 0), 62), xb = min(max(ix, 0), 62);
        float wAx = 0.0f, wBx = 0.0f;
        if (vx0) { if (min(max(ix, 0), 63) == xb) wAx += 1.0f - ax; else wBx += 1.0f - ax; }
        if (vx1) { if (min(max(ix + 1, 0), 63) == xb) wAx += ax; else wBx += ax; }
        float wy0 = 0.0f, wy1 = 0.0f;
        if (vy0) { if (min(max(iy, 0), 63) == yb) wy0 += 1.0f - ay; else wy1 += 1.0f - ay; }
        if (vy1) { if (min(max(iy + 1, 0), 63) == yb) wy0 += ay; else wy1 += ay; }
        wy0 *= m; wy1 *= m;
        s_ii[e] = yb * 64 + xb;
        s_ww[e] = make_float4(wy0 * wAx, wy0 * wBx, wy1 * wAx, wy1 * wBx);
    }
}

// ---------------- DCNv1 mid conv: interleaved-pair quad gather -----------------------
__global__ void __launch_bounds__(256)
dcn_mid(const uint4* __restrict__ hq,
        const unsigned* __restrict__ Ahi, const unsigned* __restrict__ Alo,
        const float* __restrict__ offs, int offBS, float* __restrict__ out) {
    extern __shared__ unsigned msm[];
    unsigned* s_bhA = msm;               // [2][2304]
    unsigned* s_blA = msm + 2 * 2304;    // [2][2304]
    __shared__ int s_ii[576];
    __shared__ float4 s_ww[576];

    const int b = blockIdx.y;
    const int tile = blockIdx.x;
    const int tid = threadIdx.x;
    const int warp = tid >> 5;
    const int lane = tid & 31;
    const int mt = warp >> 1;
    const int nh = warp & 1;
    const int q = lane >> 2;

    build_tables<false>(tid, tile, b, offs, offBS, nullptr, s_ii, s_ww);
    __syncthreads();

    float acc[4][4];
#pragma unroll
    for (int nt = 0; nt < 4; nt++)
#pragma unroll
        for (int r = 0; r < 4; r++) acc[nt][r] = 0.0f;

    const int p = tid & 63;
    const int jp0 = tid >> 6;
    const int perm = (p & 7) * 8 + (p >> 3);

    auto gather = [&](int slab, int buf) {
        unsigned* bh = s_bhA + buf * 2304;
        unsigned* bl = s_blA + buf * 2304;
        int r = slab * 64 + p;              // slab == tap
        int ib = s_ii[r];
        float4 w4 = s_ww[r];
        const uint4* xc = hq + ((size_t)b * 32 + jp0) * HW;
        int jp = jp0;
#pragma unroll
        for (int i = 0; i < 8; i++) {
            uint4 Q = __ldg(xc + ib);
            float va = dot2h(w4, Q.x, Q.y);
            float vb = dot2h(w4, Q.z, Q.w);
            __half vah = __float2half(va), vbh = __float2half(vb);
            __half val = __float2half(va - __half2float(vah));
            __half vbl = __float2half(vb - __half2float(vbh));
            bh[jp * 72 + perm] = pack_h2(vah, vbh);
            bl[jp * 72 + perm] = pack_h2(val, vbl);
            jp += 4;
            xc += 4 * HW;
        }
    };

    gather(0, 0);
    __syncthreads();

    for (int slab = 0; slab < 9; slab++) {
        if (slab < 8) gather(slab + 1, (slab + 1) & 1);
        const unsigned* sbh = s_bhA + (slab & 1) * 2304;
        const unsigned* sbl = s_blA + (slab & 1) * 2304;
#pragma unroll
        for (int kc = 0; kc < 4; kc++) {
            int kcg = slab * 4 + kc;
            uint4 Ah = __ldg((const uint4*)(Ahi + (((size_t)kcg * 4 + mt) * 32 + lane) * 4));
            uint4 Al = __ldg((const uint4*)(Alo + (((size_t)kcg * 4 + mt) * 32 + lane) * 4));
            int boff = (kc * 8 + (lane & 3)) * 72 + q * 8 + nh * 4;
            uint4 B0h = *(const uint4*)(sbh + boff);
            uint4 B1h = *(const uint4*)(sbh + boff + 4 * 72);
            uint4 B0l = *(const uint4*)(sbl + boff);
            uint4 B1l = *(const uint4*)(sbl + boff + 4 * 72);
            mma_f16(acc[0], Ah.x, Ah.y, Ah.z, Ah.w, B0h.x, B1h.x);
            mma_f16(acc[0], Ah.x, Ah.y, Ah.z, Ah.w, B0l.x, B1l.x);
            mma_f16(acc[0], Al.x, Al.y, Al.z, Al.w, B0h.x, B1h.x);
            mma_f16(acc[1], Ah.x, Ah.y, Ah.z, Ah.w, B0h.y, B1h.y);
            mma_f16(acc[1], Ah.x, Ah.y, Ah.z, Ah.w, B0l.y, B1l.y);
            mma_f16(acc[1], Al.x, Al.y, Al.z, Al.w, B0h.y, B1h.y);
            mma_f16(acc[2], Ah.x, Ah.y, Ah.z, Ah.w, B0h.z, B1h.z);
            mma_f16(acc[2], Ah.x, Ah.y, Ah.z, Ah.w, B0l.z, B1l.z);
            mma_f16(acc[2], Al.x, Al.y, Al.z, Al.w, B0h.z, B1h.z);
            mma_f16(acc[3], Ah.x, Ah.y, Ah.z, Ah.w, B0h.w, B1h.w);
            mma_f16(acc[3], Ah.x, Ah.y, Ah.z, Ah.w, B0l.w, B1l.w);
            mma_f16(acc[3], Al.x, Al.y, Al.z, Al.w, B0h.w, B1h.w);
        }
        __syncthreads();
    }

    int o = mt * 16 + (lane >> 2);
    int colb = tile * 64 + nh * 32 + (lane & 3) * 2;
    float* o0 = out + ((size_t)b * 64 + o) * HW + colb;
    float* o1 = o0 + 8 * HW;
#pragma unroll
    for (int nt = 0; nt < 4; nt++) {
        *reinterpret_cast<float2*>(o0 + nt * 8) = make_float2(acc[nt][0], acc[nt][1]);
        *reinterpret_cast<float2*>(o1 + nt * 8) = make_float2(acc[nt][2], acc[nt][3]);
    }
}

// ---------------- final modulated DCNv2: interleaved-pair quad gather ----------------
__global__ void __launch_bounds__(256)
dcn_final_f16(const uint4* __restrict__ xq, const unsigned* __restrict__ Af,
              const float* __restrict__ offs, const float* __restrict__ msk,
              const float* __restrict__ bias, float* __restrict__ out) {
    __shared__ unsigned s_bA[2][32 * 72];
    __shared__ int s_ii[576];
    __shared__ float4 s_ww[576];

    const int b = blockIdx.y;
    const int tile = blockIdx.x;
    const int tid = threadIdx.x;
    const int warp = tid >> 5;
    const int lane = tid & 31;
    const int q = lane >> 2;

    build_tables<true>(tid, tile, b, offs, 36 * HW, msk, s_ii, s_ww);
    __syncthreads();

    float acc[2][8][4];
#pragma unroll
    for (int mtl = 0; mtl < 2; mtl++)
#pragma unroll
        for (int nt = 0; nt < 8; nt++)
#pragma unroll
            for (int r = 0; r < 4; r++) acc[mtl][nt][r] = 0.0f;

    const int p = tid & 63;
    const int jp0 = tid >> 6;
    const int perm = (p & 7) * 8 + (p >> 3);

    auto gather = [&](int slab, int buf) {
        unsigned* bdst = s_bA[buf];
        int kk = slab >> 2;
        int r = kk * 64 + p;
        int ib = s_ii[r];
        float4 w4 = s_ww[r];
        const uint4* xc = xq + ((size_t)b * 128 + (slab & 3) * 32 + jp0) * HW;
        int jp = jp0;
#pragma unroll
        for (int i = 0; i < 8; i++) {
            uint4 Q = __ldg(xc + ib);
            float va = dot2h(w4, Q.x, Q.y);
            float vb = dot2h(w4, Q.z, Q.w);
            bdst[jp * 72 + perm] = pack_h2(__float2half(va), __float2half(vb));
            jp += 4;
            xc += 4 * HW;
        }
    };

    gather(0, 0);
    __syncthreads();

    for (int slab = 0; slab < 36; slab++) {
        if (slab < 35) gather(slab + 1, (slab + 1) & 1);
        const unsigned* sb = s_bA[slab & 1];
#pragma unroll
        for (int kc = 0; kc < 4; kc++) {
            int kcg = slab * 4 + kc;
            const unsigned* ap = Af + (((size_t)kcg * 16 + warp * 2) * 32 + lane) * 4;
            uint4 A0 = __ldg((const uint4*)ap);
            uint4 A1 = __ldg((const uint4*)(ap + 128));

            int boff = (kc * 8 + (lane & 3)) * 72 + q * 8;
            uint4 B0a = *(const uint4*)(sb + boff);
            uint4 B0b = *(const uint4*)(sb + boff + 4);
            uint4 B1a = *(const uint4*)(sb + boff + 4 * 72);
            uint4 B1b = *(const uint4*)(sb + boff + 4 * 72 + 4);
            mma_f16(acc[0][0], A0.x, A0.y, A0.z, A0.w, B0a.x, B1a.x);
            mma_f16(acc[1][0], A1.x, A1.y, A1.z, A1.w, B0a.x, B1a.x);
            mma_f16(acc[0][1], A0.x, A0.y, A0.z, A0.w, B0a.y, B1a.y);
            mma_f16(acc[1][1], A1.x, A1.y, A1.z, A1.w, B0a.y, B1a.y);
            mma_f16(acc[0][2], A0.x, A0.y, A0.z, A0.w, B0a.z, B1a.z);
            mma_f16(acc[1][2], A1.x, A1.y, A1.z, A1.w, B0a.z, B1a.z);
            mma_f16(acc[0][3], A0.x, A0.y, A0.z, A0.w, B0a.w, B1a.w);
            mma_f16(acc[1][3], A1.x, A1.y, A1.z, A1.w, B0a.w, B1a.w);
            mma_f16(acc[0][4], A0.x, A0.y, A0.z, A0.w, B0b.x, B1b.x);
            mma_f16(acc[1][4], A1.x, A1.y, A1.z, A1.w, B0b.x, B1b.x);
            mma_f16(acc[0][5], A0.x, A0.y, A0.z, A0.w, B0b.y, B1b.y);
            mma_f16(acc[1][5], A1.x, A1.y, A1.z, A1.w, B0b.y, B1b.y);
            mma_f16(acc[0][6], A0.x, A0.y, A0.z, A0.w, B0b.z, B1b.z);
            mma_f16(acc[1][6], A1.x, A1.y, A1.z, A1.w, B0b.z, B1b.z);
            mma_f16(acc[0][7], A0.x, A0.y, A0.z, A0.w, B0b.w, B1b.w);
            mma_f16(acc[1][7], A1.x, A1.y, A1.z, A1.w, B0b.w, B1b.w);
        }
        __syncthreads();
    }

#pragma unroll
    for (int mtl = 0; mtl < 2; mtl++) {
        int o = warp * 32 + mtl * 16 + (lane >> 2);
        float b_lo = __ldg(bias + o);
        float b_hi = __ldg(bias + o + 8);
        float* o0 = out + ((size_t)b * 256 + o) * HW + tile * 64 + (lane & 3) * 2;
        float* o1 = o0 + 8 * HW;
#pragma unroll
        for (int nt = 0; nt < 8; nt++) {
            *reinterpret_cast<float2*>(o0 + nt * 8) =
                make_float2(acc[mtl][nt][0] + b_lo, acc[mtl][nt][1] + b_lo);
            *reinterpret_cast<float2*>(o1 + nt * 8) =
                make_float2(acc[mtl][nt][2] + b_hi, acc[mtl][nt][3] + b_hi);
        }
    }
}

// ---------------- host launcher ------------------------------------------------------
extern "C" void kernel_launch(void* const* d_in, const int* in_sizes, int n_in,
                              void* d_out, int out_size) {
    const float* x       = (const float*)d_in[0];
    const float* S       = (const float*)d_in[1];
    const float* sp_w1   = (const float*)d_in[2];
    const float* sp_b1   = (const float*)d_in[3];
    const float* sp_s1   = (const float*)d_in[4];
    const float* sp_o1   = (const float*)d_in[5];
    const float* sp_w2   = (const float*)d_in[6];
    const float* sp_b2   = (const float*)d_in[7];
    const float* sp_s2   = (const float*)d_in[8];
    const float* sp_o2   = (const float*)d_in[9];
    const float* sp_w3   = (const float*)d_in[10];
    const float* sp_b3   = (const float*)d_in[11];
    const float* sp_s3   = (const float*)d_in[12];
    const float* sp_o3   = (const float*)d_in[13];
    const float* off_w   = (const float*)d_in[14];
    const float* off_b   = (const float*)d_in[15];
    const float* dcoff_w = (const float*)d_in[16];
    const float* dcoff_b = (const float*)d_in[17];
    const float* dc_w    = (const float*)d_in[18];
    const float* m_w     = (const float*)d_in[19];
    const float* m_b     = (const float*)d_in[20];
    const float* weight  = (const float*)d_in[21];
    const float* bias    = (const float*)d_in[22];

    float *h1, *h2, *h3, *feat, *off, *mask, *b36;
    uint4 *xqi, *hqi3;
    unsigned *Af, *Ah2, *Al2, *Ah3, *Al3, *Ahdc, *Aldc, *Ah36, *Al36;
    cudaGetSymbolAddress((void**)&h1,   g_h1);
    cudaGetSymbolAddress((void**)&h2,   g_h2);
    cudaGetSymbolAddress((void**)&h3,   g_h3);
    cudaGetSymbolAddress((void**)&feat, g_feat);
    cudaGetSymbolAddress((void**)&off,  g_off);
    cudaGetSymbolAddress((void**)&mask, g_mask);
    cudaGetSymbolAddress((void**)&b36,  g_b36);
    cudaGetSymbolAddress((void**)&xqi,  g_xqi);
    cudaGetSymbolAddress((void**)&hqi3, g_hqi3);
    cudaGetSymbolAddress((void**)&Af,   g_Af);
    cudaGetSymbolAddress((void**)&Ah2,  g_Ah2);
    cudaGetSymbolAddress((void**)&Al2,  g_Al2);
    cudaGetSymbolAddress((void**)&Ah3,  g_Ah3);
    cudaGetSymbolAddress((void**)&Al3,  g_Al3);
    cudaGetSymbolAddress((void**)&Ahdc, g_Ahdc);
    cudaGetSymbolAddress((void**)&Aldc, g_Aldc);
    cudaGetSymbolAddress((void**)&Ah36, g_Ah36);
    cudaGetSymbolAddress((void**)&Al36, g_Al36);

    const int SMEM_SHIFT = 4 * 3456 * 4;   // 55296 (separate hi/lo, R12 layout)
    const int SMEM_MID   = 4 * 2304 * 4;   // 36864
    cudaFuncSetAttribute(conv_shift<1>,
                         cudaFuncAttributeMaxDynamicSharedMemorySize, SMEM_SHIFT);
    cudaFuncSetAttribute(conv_shift<2>,
                         cudaFuncAttributeMaxDynamicSharedMemorySize, SMEM_SHIFT);
    cudaFuncSetAttribute(dcn_mid,
                         cudaFuncAttributeMaxDynamicSharedMemorySize, SMEM_MID);

    auto tgrid = [](int n) { return (n + 255) / 256; };
    dim3 grid(64, BATCH);

    prep_shift_f16<<<tgrid(64 * 576), 256>>>(sp_w2, Ah2, Al2, 64);                // 0
    prep_shift_f16<<<tgrid(64 * 576), 256>>>(sp_w3, Ah3, Al3, 64);                // 1
    sp1_kernel<<<grid, 256>>>(S, sp_w1, sp_b1, sp_s1, sp_o1, h1);                 // 2
    conv_shift<1><<<grid, 256, SMEM_SHIFT>>>(h1, Ah2, Al2,
                                             sp_b2, sp_s2, sp_o2, h2, 64);        // 3 <- ncu
    conv_shift<1><<<grid, 256, SMEM_SHIFT>>>(h2, Ah3, Al3,
                                             sp_b3, sp_s3, sp_o3, h3, 64);        // 4
    quad_h2i<<<tgrid(BATCH * 128 * HW), 256>>>(x, xqi, BATCH * 128 * HW, 128);    // 5
    prep_shift_w36<<<tgrid(64 * 576), 256>>>(off_w, dcoff_w, Ah36, Al36);         // 6
    concat_bias36<<<1, 36>>>(off_b, dcoff_b, b36);                                // 7
    prep_middc_tap<<<tgrid(64 * 576), 256>>>(dc_w, Ahdc, Aldc);                   // 8
    conv_shift<2><<<grid, 256, SMEM_SHIFT>>>(h3, Ah36, Al36,
                                             b36, nullptr, nullptr, off, 36);     // 9
    quad_h2i<<<tgrid(BATCH * 32 * HW), 256>>>(h3, hqi3, BATCH * 32 * HW, 32);     // 10
    dcn_mid<<<grid, 256, SMEM_MID>>>(hqi3, Ahdc, Aldc, off + 18 * HW, 36 * HW, feat); // 11
    mask_kernel<<<(BATCH * HW + 255) / 256, 256>>>(feat, m_w, m_b, mask);         // 12
    prep_final_f16<<<tgrid(256 * 2304), 256>>>(weight, Af);                       // 13
    dcn_final_f16<<<grid, 256>>>(xqi, Af, off, mask, bias, (float*)d_out);        // 14
}

// round 15
// speedup vs baseline: 1.1974x; 1.1266x over previous
#include <cuda_runtime.h>
#include <cuda_fp16.h>
#include <math.h>
#include <stdint.h>

#define HW 4096     // 64*64
#define BATCH 8

// ---------------- scratch (static device globals; no allocation) ----------------
__device__ float g_h1  [BATCH*64*HW];
__device__ float g_h2  [BATCH*64*HW];
__device__ float g_h3  [BATCH*64*HW];
__device__ float g_feat[BATCH*64*HW];
__device__ float g_off [BATCH*36*HW];   // ch 0..17 = offset, 18..35 = dc_off
__device__ float g_mask[BATCH*9*HW];
__device__ float g_b36 [36];

// channel-pair-interleaved f16 quads
__device__ uint4 g_xqi [BATCH*128*HW];  // 64MB (x, 256 ch -> 128 pairs)
__device__ uint4 g_hqi3[BATCH*32*HW];   // 16MB (h3, 64 ch -> 32 pairs)

// f16 fragment-packed weights (each u32 = 2 f16 along K)
__device__ unsigned g_Af[144*16*32*4];
#define MIDA (36*4*32*4)
__device__ unsigned g_Ah2 [MIDA], g_Al2 [MIDA];   // shift-order
__device__ unsigned g_Ah3 [MIDA], g_Al3 [MIDA];   // shift-order
__device__ unsigned g_Ah36[MIDA], g_Al36[MIDA];   // shift-order
__device__ unsigned g_Ahdc[MIDA], g_Aldc[MIDA];   // tap-major (K=kk*64+c)

// ---------------- helpers ------------------------------------------------------------
__device__ __forceinline__ void mma_f16(float* acc, unsigned a0, unsigned a1,
                                        unsigned a2, unsigned a3,
                                        unsigned b0, unsigned b1) {
    asm volatile(
        "mma.sync.aligned.m16n8k16.row.col.f32.f16.f16.f32 "
        "{%0,%1,%2,%3}, {%4,%5,%6,%7}, {%8,%9}, {%0,%1,%2,%3};"
        : "+f"(acc[0]), "+f"(acc[1]), "+f"(acc[2]), "+f"(acc[3])
        : "r"(a0), "r"(a1), "r"(a2), "r"(a3), "r"(b0), "r"(b1));
}

__device__ __forceinline__ void frag_coords(int om, int kk, int& lane, int& reg, int& half) {
    int kpair = kk >> 1;
    half = kk & 1;
    lane = (om & 7) * 4 + (kpair & 3);
    reg = (om >> 3) + ((kpair >> 2) << 1);
}

__device__ __forceinline__ unsigned pack_h2(__half lo, __half hi) {
    return (unsigned)__half_as_ushort(lo) | ((unsigned)__half_as_ushort(hi) << 16);
}

__device__ __forceinline__ float dot2h(float4 w, unsigned qa, unsigned qb) {
    float2 f0 = __half22float2(*reinterpret_cast<__half2*>(&qa));
    float2 f1 = __half22float2(*reinterpret_cast<__half2*>(&qb));
    return w.x * f0.x + w.y * f0.y + w.z * f1.x + w.w * f1.y;
}

// ---------------- weight prep kernels -------------------------------------------------
__global__ void prep_middc_tap(const float* __restrict__ w, unsigned* __restrict__ hi,
                               unsigned* __restrict__ lo) {
    int i = blockIdx.x * blockDim.x + threadIdx.x;
    if (i >= 64 * 576) return;
    int K = i % 576;
    int o = i / 576;
    float v = w[o * 576 + K];
    __half vh = __float2half(v);
    __half vl = __float2half(v - __half2float(vh));
    int c = K / 9, kk = K - c * 9;
    int Kn = kk * 64 + c;
    int kc = Kn >> 4, kwi = Kn & 15;
    int lane, reg, half;
    frag_coords(o & 15, kwi, lane, reg, half);
    size_t base = ((((size_t)kc * 4 + (o >> 4)) * 32 + lane) * 4 + reg) * 2 + half;
    ((__half*)hi)[base] = vh;
    ((__half*)lo)[base] = vl;
}

__global__ void prep_shift_f16(const float* __restrict__ w, unsigned* __restrict__ hi,
                               unsigned* __restrict__ lo, int O) {
    int i = blockIdx.x * blockDim.x + threadIdx.x;
    if (i >= 64 * 576) return;
    int K = i % 576;
    int o = i / 576;
    float v = (o < O) ? w[o * 576 + K] : 0.0f;
    __half vh = __float2half(v);
    __half vl = __float2half(v - __half2float(vh));
    int c = K / 9, kk = K % 9;
    int slab = c >> 5, cl = c & 31;
    int kcg = (slab * 9 + kk) * 2 + (cl >> 4);
    int lane, reg, half;
    frag_coords(o & 15, cl & 15, lane, reg, half);
    size_t base = ((((size_t)kcg * 4 + (o >> 4)) * 32 + lane) * 4 + reg) * 2 + half;
    ((__half*)hi)[base] = vh;
    ((__half*)lo)[base] = vl;
}

__global__ void prep_shift_w36(const float* __restrict__ wa, const float* __restrict__ wb,
                               unsigned* __restrict__ hi, unsigned* __restrict__ lo) {
    int i = blockIdx.x * blockDim.x + threadIdx.x;
    if (i >= 64 * 576) return;
    int K = i % 576;
    int o = i / 576;
    float v = 0.0f;
    if (o < 18) v = wa[o * 576 + K];
    else if (o < 36) v = wb[(o - 18) * 576 + K];
    __half vh = __float2half(v);
    __half vl = __float2half(v - __half2float(vh));
    int c = K / 9, kk = K % 9;
    int slab = c >> 5, cl = c & 31;
    int kcg = (slab * 9 + kk) * 2 + (cl >> 4);
    int lane, reg, half;
    frag_coords(o & 15, cl & 15, lane, reg, half);
    size_t base = ((((size_t)kcg * 4 + (o >> 4)) * 32 + lane) * 4 + reg) * 2 + half;
    ((__half*)hi)[base] = vh;
    ((__half*)lo)[base] = vl;
}

// final: tap-major Kn = kk*256 + c
__global__ void prep_final_f16(const float* __restrict__ w, unsigned* __restrict__ dst) {
    int i = blockIdx.x * blockDim.x + threadIdx.x;
    if (i >= 256 * 2304) return;
    int K = i % 2304;
    int o = i / 2304;
    int c = K / 9, kk = K - c * 9;
    int Kn = kk * 256 + c;
    int kc = Kn >> 4, kwi = Kn & 15;
    int lane, reg, half;
    frag_coords(o & 15, kwi, lane, reg, half);
    size_t base = ((((size_t)kc * 16 + (o >> 4)) * 32 + lane) * 4 + reg) * 2 + half;
    ((__half*)dst)[base] = __float2half(w[i]);
}

__global__ void concat_bias36(const float* __restrict__ a, const float* __restrict__ b,
                              float* __restrict__ dst) {
    int i = threadIdx.x;
    if (i < 18) dst[i] = a[i];
    else if (i < 36) dst[i] = b[i - 18];
}

// ---------------- channel-pair interleaved f16 quad shingle ---------------------------
__global__ void quad_h2i(const float* __restrict__ src, uint4* __restrict__ dst,
                         int total, int C2) {
    int i = blockIdx.x * blockDim.x + threadIdx.x;
    if (i >= total) return;
    int pix = i & (HW - 1);
    int bc2 = i >> 12;
    int b = bc2 / C2;
    int c2 = bc2 - b * C2;
    int xx = pix & 63, yy = pix >> 6;
    const float* s0 = src + ((size_t)(b * 2 * C2 + c2 * 2)) * HW;
    const float* s1 = s0 + HW;
    bool okx = (xx < 63), oky = (yy < 63);
    float A0 = s0[pix];
    float B0 = okx ? s0[pix + 1] : 0.0f;
    float C0 = oky ? s0[pix + 64] : 0.0f;
    float D0 = (okx && oky) ? s0[pix + 65] : 0.0f;
    float A1 = s1[pix];
    float B1 = okx ? s1[pix + 1] : 0.0f;
    float C1 = oky ? s1[pix + 64] : 0.0f;
    float D1 = (okx && oky) ? s1[pix + 65] : 0.0f;
    dst[i] = make_uint4(pack_h2(__float2half(A0), __float2half(B0)),
                        pack_h2(__float2half(C0), __float2half(D0)),
                        pack_h2(__float2half(A1), __float2half(B1)),
                        pack_h2(__float2half(C1), __float2half(D1)));
}

// ---------------- 1x1 conv + sigmoid -------------------------------------------------
__global__ void mask_kernel(const float* __restrict__ feat, const float* __restrict__ mw,
                            const float* __restrict__ mb, float* __restrict__ mask) {
    int i = blockIdx.x * blockDim.x + threadIdx.x;
    if (i >= BATCH * HW) return;
    int b = i >> 12;
    int pix = i & (HW - 1);
    float acc[9];
#pragma unroll
    for (int o = 0; o < 9; o++) acc[o] = __ldg(mb + o);
    const float* fp = feat + (size_t)b * 64 * HW + pix;
    for (int c = 0; c < 64; c++) {
        float v = __ldg(fp + c * HW);
#pragma unroll
        for (int o = 0; o < 9; o++) acc[o] += v * __ldg(mw + o * 64 + c);
    }
#pragma unroll
    for (int o = 0; o < 9; o++)
        mask[((size_t)b * 9 + o) * HW + pix] = 1.0f / (1.0f + expf(-acc[o]));
}

// ---------------- sp1: fused resize + conv3x3 (CIN=3) + BN + ReLU, fp32 --------------
__device__ __forceinline__ float resize_at(const float* __restrict__ p, int y, int x) {
    const float scale = 127.0f / 63.0f;
    float ys = y * scale, xs = x * scale;
    float fy = floorf(ys), fx = floorf(xs);
    int y0 = (int)fy, x0 = (int)fx;
    int y1 = min(y0 + 1, 127), x1 = min(x0 + 1, 127);
    float wy = ys - fy, wx = xs - fx;
    return p[y0 * 128 + x0] * (1.0f - wy) * (1.0f - wx)
         + p[y0 * 128 + x1] * (1.0f - wy) * wx
         + p[y1 * 128 + x0] * wy * (1.0f - wx)
         + p[y1 * 128 + x1] * wy * wx;
}

__global__ void __launch_bounds__(256)
sp1_kernel(const float* __restrict__ S, const float* __restrict__ w1,
           const float* __restrict__ e_b, const float* __restrict__ e_s,
           const float* __restrict__ e_o, float* __restrict__ out) {
    __shared__ __align__(16) float s_t[576];
    const int b = blockIdx.y;
    const int tile = blockIdx.x;
    const int tid = threadIdx.x;
    const int o = tid & 63;
    const int pbase = (tid >> 6) * 16;

    float acc[16];
#pragma unroll
    for (int j = 0; j < 16; j++) acc[j] = 0.0f;

    for (int c = 0; c < 3; c++) {
        const float* Sc = S + (size_t)(b * 3 + c) * 128 * 128;
        for (int e = tid; e < 576; e += 256) {
            int k = e >> 6, p = e & 63;
            int yy = tile + k / 3 - 1;
            int xx = p + k % 3 - 1;
            s_t[e] = ((unsigned)yy < 64u && (unsigned)xx < 64u)
                         ? resize_at(Sc, yy, xx) : 0.0f;
        }
        __syncthreads();

        float wv[9];
#pragma unroll
        for (int k = 0; k < 9; k++) wv[k] = __ldg(w1 + o * 27 + c * 9 + k);

#pragma unroll
        for (int k = 0; k < 9; k++) {
            const float4* sp = reinterpret_cast<const float4*>(s_t + k * 64 + pbase);
#pragma unroll
            for (int j4 = 0; j4 < 4; j4++) {
                float4 sv = sp[j4];
                acc[j4 * 4 + 0] += wv[k] * sv.x;
                acc[j4 * 4 + 1] += wv[k] * sv.y;
                acc[j4 * 4 + 2] += wv[k] * sv.z;
                acc[j4 * 4 + 3] += wv[k] * sv.w;
            }
        }
        __syncthreads();
    }

    float bb = __ldg(e_b + o), ssc = __ldg(e_s + o), oof = __ldg(e_o + o);
    float* op = out + ((size_t)b * 64 + o) * HW + tile * 64 + pbase;
#pragma unroll
    for (int j = 0; j < 16; j++)
        op[j] = fmaxf((acc[j] + bb) * ssc + oof, 0.0f);
}

// ---------------- plain conv3x3: single-f16 B, 2-term weights ------------------------
template <int EPI>
__global__ void __launch_bounds__(256)
conv_shift(const float* __restrict__ inp,
           const unsigned* __restrict__ Ahi, const unsigned* __restrict__ Alo,
           const float* __restrict__ e_b, const float* __restrict__ e_s,
           const float* __restrict__ e_o, float* __restrict__ out, int Oact) {
    extern __shared__ unsigned csm[];    // [2][3456] single-f16 B

    const int b = blockIdx.y;
    const int tile = blockIdx.x;
    const int tid = threadIdx.x;
    const int warp = tid >> 5;
    const int lane = tid & 31;
    const int mt = warp >> 1;
    const int nh = warp & 1;

    float acc[4][4];
#pragma unroll
    for (int nt = 0; nt < 4; nt++)
#pragma unroll
        for (int r = 0; r < 4; r++) acc[nt][r] = 0.0f;

    const float* xb = inp + (size_t)b * 64 * HW;

    auto fill = [&](int slab, int buf) {
        unsigned* bh = csm + buf * 3456;
        for (int e = tid; e < 3168; e += 256) {
            int r = e / 1056;
            int rem = e - r * 1056;
            int cp = rem / 66;
            int col = rem - cp * 66;
            int yy = tile - 1 + r;
            int px = col - 1;
            bool ok = ((unsigned)yy < 64u) && ((unsigned)px < 64u);
            const float* p0 = xb + (size_t)(slab * 32 + cp * 2) * HW + yy * 64 + px;
            float v0 = ok ? __ldg(p0) : 0.0f;
            float v1 = ok ? __ldg(p0 + HW) : 0.0f;
            bh[(r * 16 + cp) * 72 + col] =
                pack_h2(__float2half(v0), __float2half(v1));
        }
    };

    fill(0, 0);
    __syncthreads();

    for (int slab = 0; slab < 2; slab++) {
        if (slab == 0) fill(1, 1);
        const unsigned* sbh = csm + slab * 3456;
#pragma unroll
        for (int t = 0; t < 9; t++) {
            const int dy = t / 3, dx = t % 3;
            const unsigned* rbh = sbh + dy * 16 * 72;
#pragma unroll
            for (int kcl = 0; kcl < 2; kcl++) {
                int kcg = (slab * 9 + t) * 2 + kcl;
                uint4 Ah = __ldg((const uint4*)(Ahi + (((size_t)kcg * 4 + mt) * 32 + lane) * 4));
                uint4 Al = __ldg((const uint4*)(Alo + (((size_t)kcg * 4 + mt) * 32 + lane) * 4));
                int boff = (kcl * 8 + (lane & 3)) * 72 + (lane >> 2) + nh * 32 + dx;
                const unsigned* bh = rbh + boff;
#pragma unroll
                for (int nt = 0; nt < 4; nt++) {
                    unsigned b0h = bh[nt * 8], b1h = bh[nt * 8 + 4 * 72];
                    mma_f16(acc[nt], Ah.x, Ah.y, Ah.z, Ah.w, b0h, b1h);
                    mma_f16(acc[nt], Al.x, Al.y, Al.z, Al.w, b0h, b1h);
                }
            }
        }
        __syncthreads();
    }

    int o = mt * 16 + (lane >> 2);
    float b0 = 0, s0 = 1, f0 = 0, b1 = 0, s1 = 1, f1 = 0;
    if (EPI == 1) {
        if (o < Oact)     { b0 = __ldg(e_b + o);     s0 = __ldg(e_s + o);     f0 = __ldg(e_o + o); }
        if (o + 8 < Oact) { b1 = __ldg(e_b + o + 8); s1 = __ldg(e_s + o + 8); f1 = __ldg(e_o + o + 8); }
    } else if (EPI == 2) {
        if (o < Oact)     b0 = __ldg(e_b + o);
        if (o + 8 < Oact) b1 = __ldg(e_b + o + 8);
    }
    int colb = tile * 64 + nh * 32 + (lane & 3) * 2;
    float* o0 = out + ((size_t)b * Oact + o) * HW + colb;
    float* o1 = o0 + 8 * HW;
#pragma unroll
    for (int nt = 0; nt < 4; nt++) {
        float v0a = acc[nt][0], v0b = acc[nt][1];
        float v1a = acc[nt][2], v1b = acc[nt][3];
        if (EPI == 1) {
            v0a = fmaxf((v0a + b0) * s0 + f0, 0.0f);
            v0b = fmaxf((v0b + b0) * s0 + f0, 0.0f);
            v1a = fmaxf((v1a + b1) * s1 + f1, 0.0f);
            v1b = fmaxf((v1b + b1) * s1 + f1, 0.0f);
        } else if (EPI == 2) {
            v0a += b0; v0b += b0; v1a += b1; v1b += b1;
        }
        if (o < Oact)
            *reinterpret_cast<float2*>(o0 + nt * 8) = make_float2(v0a, v0b);
        if (o + 8 < Oact)
            *reinterpret_cast<float2*>(o1 + nt * 8) = make_float2(v1a, v1b);
    }
}

// ---------------- deform table build: 1 int + 1 float4 -------------------------------
template <bool MASKED>
__device__ __forceinline__ void build_tables(
    int tid, int tile, int b, const float* __restrict__ offs, int offBS,
    const float* __restrict__ msk, int* s_ii, float4* s_ww) {
    for (int e = tid; e < 576; e += 256) {
        int k = e >> 6, p = e & 63;
        int pix = tile * 64 + p;
        float py = (float)(tile - 1 + k / 3)
                 + offs[(size_t)b * offBS + (2 * k) * HW + pix];
        float px = (float)(p - 1 + k % 3)
                 + offs[(size_t)b * offBS + (2 * k + 1) * HW + pix];
        float m = MASKED ? msk[(size_t)b * 9 * HW + k * HW + pix] : 1.0f;
        float fy = floorf(py), fx = floorf(px);
        int iy = (int)fy, ix = (int)fx;
        float ay = py - fy, ax = px - fx;
        bool vy0 = (iy >= 0) && (iy < 64);
        bool vy1 = (iy >= -1) && (iy < 63);
        bool vx0 = (ix >= 0) && (ix < 64);
        bool vx1 = (ix >= -1) && (ix < 63);
        int yb = min(max(iy, 0), 62), xb = min(max(ix, 0), 62);
        float wAx = 0.0f, wBx = 0.0f;
        if (vx0) { if (min(max(ix, 0), 63) == xb) wAx += 1.0f - ax; else wBx += 1.0f - ax; }
        if (vx1) { if (min(max(ix + 1, 0), 63) == xb) wAx += ax; else wBx += ax; }
        float wy0 = 0.0f, wy1 = 0.0f;
        if (vy0) { if (min(max(iy, 0), 63) == yb) wy0 += 1.0f - ay; else wy1 += 1.0f - ay; }
        if (vy1) { if (min(max(iy + 1, 0), 63) == yb) wy0 += ay; else wy1 += ay; }
        wy0 *= m; wy1 *= m;
        s_ii[e] = yb * 64 + xb;
        s_ww[e] = make_float4(wy0 * wAx, wy0 * wBx, wy1 * wAx, wy1 * wBx);
    }
}

// ---------------- DCNv1 mid conv: single-f16 B, 2-term weights -----------------------
__global__ void __launch_bounds__(256)
dcn_mid(const uint4* __restrict__ hq,
        const unsigned* __restrict__ Ahi, const unsigned* __restrict__ Alo,
        const float* __restrict__ offs, int offBS, float* __restrict__ out) {
    extern __shared__ unsigned msm[];    // [2][2304]
    __shared__ int s_ii[576];
    __shared__ float4 s_ww[576];

    const int b = blockIdx.y;
    const int tile = blockIdx.x;
    const int tid = threadIdx.x;
    const int warp = tid >> 5;
    const int lane = tid & 31;
    const int mt = warp >> 1;
    const int nh = warp & 1;
    const int q = lane >> 2;

    build_tables<false>(tid, tile, b, offs, offBS, nullptr, s_ii, s_ww);
    __syncthreads();

    float acc[4][4];
#pragma unroll
    for (int nt = 0; nt < 4; nt++)
#pragma unroll
        for (int r = 0; r < 4; r++) acc[nt][r] = 0.0f;

    const int p = tid & 63;
    const int jp0 = tid >> 6;
    const int perm = (p & 7) * 8 + (p >> 3);

    auto gather = [&](int slab, int buf) {
        unsigned* bh = msm + buf * 2304;
        int r = slab * 64 + p;              // slab == tap
        int ib = s_ii[r];
        float4 w4 = s_ww[r];
        const uint4* xc = hq + ((size_t)b * 32 + jp0) * HW;
        int jp = jp0;
#pragma unroll
        for (int i = 0; i < 8; i++) {
            uint4 Q = __ldg(xc + ib);
            float va = dot2h(w4, Q.x, Q.y);
            float vb = dot2h(w4, Q.z, Q.w);
            bh[jp * 72 + perm] = pack_h2(__float2half(va), __float2half(vb));
            jp += 4;
            xc += 4 * HW;
        }
    };

    gather(0, 0);
    __syncthreads();

    for (int slab = 0; slab < 9; slab++) {
        if (slab < 8) gather(slab + 1, (slab + 1) & 1);
        const unsigned* sbh = msm + (slab & 1) * 2304;
#pragma unroll
        for (int kc = 0; kc < 4; kc++) {
            int kcg = slab * 4 + kc;
            uint4 Ah = __ldg((const uint4*)(Ahi + (((size_t)kcg * 4 + mt) * 32 + lane) * 4));
            uint4 Al = __ldg((const uint4*)(Alo + (((size_t)kcg * 4 + mt) * 32 + lane) * 4));
            int boff = (kc * 8 + (lane & 3)) * 72 + q * 8 + nh * 4;
            uint4 B0h = *(const uint4*)(sbh + boff);
            uint4 B1h = *(const uint4*)(sbh + boff + 4 * 72);
            mma_f16(acc[0], Ah.x, Ah.y, Ah.z, Ah.w, B0h.x, B1h.x);
            mma_f16(acc[0], Al.x, Al.y, Al.z, Al.w, B0h.x, B1h.x);
            mma_f16(acc[1], Ah.x, Ah.y, Ah.z, Ah.w, B0h.y, B1h.y);
            mma_f16(acc[1], Al.x, Al.y, Al.z, Al.w, B0h.y, B1h.y);
            mma_f16(acc[2], Ah.x, Ah.y, Ah.z, Ah.w, B0h.z, B1h.z);
            mma_f16(acc[2], Al.x, Al.y, Al.z, Al.w, B0h.z, B1h.z);
            mma_f16(acc[3], Ah.x, Ah.y, Ah.z, Ah.w, B0h.w, B1h.w);
            mma_f16(acc[3], Al.x, Al.y, Al.z, Al.w, B0h.w, B1h.w);
        }
        __syncthreads();
    }

    int o = mt * 16 + (lane >> 2);
    int colb = tile * 64 + nh * 32 + (lane & 3) * 2;
    float* o0 = out + ((size_t)b * 64 + o) * HW + colb;
    float* o1 = o0 + 8 * HW;
#pragma unroll
    for (int nt = 0; nt < 4; nt++) {
        *reinterpret_cast<float2*>(o0 + nt * 8) = make_float2(acc[nt][0], acc[nt][1]);
        *reinterpret_cast<float2*>(o1 + nt * 8) = make_float2(acc[nt][2], acc[nt][3]);
    }
}

// ---------------- final modulated DCNv2: interleaved-pair quad gather ----------------
__global__ void __launch_bounds__(256)
dcn_final_f16(const uint4* __restrict__ xq, const unsigned* __restrict__ Af,
              const float* __restrict__ offs, const float* __restrict__ msk,
              const float* __restrict__ bias, float* __restrict__ out) {
    __shared__ unsigned s_bA[2][32 * 72];
    __shared__ int s_ii[576];
    __shared__ float4 s_ww[576];

    const int b = blockIdx.y;
    const int tile = blockIdx.x;
    const int tid = threadIdx.x;
    const int warp = tid >> 5;
    const int lane = tid & 31;
    const int q = lane >> 2;

    build_tables<true>(tid, tile, b, offs, 36 * HW, msk, s_ii, s_ww);
    __syncthreads();

    float acc[2][8][4];
#pragma unroll
    for (int mtl = 0; mtl < 2; mtl++)
#pragma unroll
        for (int nt = 0; nt < 8; nt++)
#pragma unroll
            for (int r = 0; r < 4; r++) acc[mtl][nt][r] = 0.0f;

    const int p = tid & 63;
    const int jp0 = tid >> 6;
    const int perm = (p & 7) * 8 + (p >> 3);

    auto gather = [&](int slab, int buf) {
        unsigned* bdst = s_bA[buf];
        int kk = slab >> 2;
        int r = kk * 64 + p;
        int ib = s_ii[r];
        float4 w4 = s_ww[r];
        const uint4* xc = xq + ((size_t)b * 128 + (slab & 3) * 32 + jp0) * HW;
        int jp = jp0;
#pragma unroll
        for (int i = 0; i < 8; i++) {
            uint4 Q = __ldg(xc + ib);
            float va = dot2h(w4, Q.x, Q.y);
            float vb = dot2h(w4, Q.z, Q.w);
            bdst[jp * 72 + perm] = pack_h2(__float2half(va), __float2half(vb));
            jp += 4;
            xc += 4 * HW;
        }
    };

    gather(0, 0);
    __syncthreads();

    for (int slab = 0; slab < 36; slab++) {
        if (slab < 35) gather(slab + 1, (slab + 1) & 1);
        const unsigned* sb = s_bA[slab & 1];
#pragma unroll
        for (int kc = 0; kc < 4; kc++) {
            int kcg = slab * 4 + kc;
            const unsigned* ap = Af + (((size_t)kcg * 16 + warp * 2) * 32 + lane) * 4;
            uint4 A0 = __ldg((const uint4*)ap);
            uint4 A1 = __ldg((const uint4*)(ap + 128));

            int boff = (kc * 8 + (lane & 3)) * 72 + q * 8;
            uint4 B0a = *(const uint4*)(sb + boff);
            uint4 B0b = *(const uint4*)(sb + boff + 4);
            uint4 B1a = *(const uint4*)(sb + boff + 4 * 72);
            uint4 B1b = *(const uint4*)(sb + boff + 4 * 72 + 4);
            mma_f16(acc[0][0], A0.x, A0.y, A0.z, A0.w, B0a.x, B1a.x);
            mma_f16(acc[1][0], A1.x, A1.y, A1.z, A1.w, B0a.x, B1a.x);
            mma_f16(acc[0][1], A0.x, A0.y, A0.z, A0.w, B0a.y, B1a.y);
            mma_f16(acc[1][1], A1.x, A1.y, A1.z, A1.w, B0a.y, B1a.y);
            mma_f16(acc[0][2], A0.x, A0.y, A0.z, A0.w, B0a.z, B1a.z);
            mma_f16(acc[1][2], A1.x, A1.y, A1.z, A1.w, B0a.z, B1a.z);
            mma_f16(acc[0][3], A0.x, A0.y, A0.z, A0.w, B0a.w, B1a.w);
            mma_f16(acc[1][3], A1.x, A1.y, A1.z, A1.w, B0a.w, B1a.w);
            mma_f16(acc[0][4], A0.x, A0.y, A0.z, A0.w, B0b.x, B1b.x);
            mma_f16(acc[1][4], A1.x, A1.y, A1.z, A1.w, B0b.x, B1b.x);
            mma_f16(acc[0][5], A0.x, A0.y, A0.z, A0.w, B0b.y, B1b.y);
            mma_f16(acc[1][5], A1.x, A1.y, A1.z, A1.w, B0b.y, B1b.y);
            mma_f16(acc[0][6], A0.x, A0.y, A0.z, A0.w, B0b.z, B1b.z);
            mma_f16(acc[1][6], A1.x, A1.y, A1.z, A1.w, B0b.z, B1b.z);
            mma_f16(acc[0][7], A0.x, A0.y, A0.z, A0.w, B0b.w, B1b.w);
            mma_f16(acc[1][7], A1.x, A1.y, A1.z, A1.w, B0b.w, B1b.w);
        }
        __syncthreads();
    }

#pragma unroll
    for (int mtl = 0; mtl < 2; mtl++) {
        int o = warp * 32 + mtl * 16 + (lane >> 2);
        float b_lo = __ldg(bias + o);
        float b_hi = __ldg(bias + o + 8);
        float* o0 = out + ((size_t)b * 256 + o) * HW + tile * 64 + (lane & 3) * 2;
        float* o1 = o0 + 8 * HW;
#pragma unroll
        for (int nt = 0; nt < 8; nt++) {
            *reinterpret_cast<float2*>(o0 + nt * 8) =
                make_float2(acc[mtl][nt][0] + b_lo, acc[mtl][nt][1] + b_lo);
            *reinterpret_cast<float2*>(o1 + nt * 8) =
                make_float2(acc[mtl][nt][2] + b_hi, acc[mtl][nt][3] + b_hi);
        }
    }
}

// ---------------- host launcher ------------------------------------------------------
extern "C" void kernel_launch(void* const* d_in, const int* in_sizes, int n_in,
                              void* d_out, int out_size) {
    const float* x       = (const float*)d_in[0];
    const float* S       = (const float*)d_in[1];
    const float* sp_w1   = (const float*)d_in[2];
    const float* sp_b1   = (const float*)d_in[3];
    const float* sp_s1   = (const float*)d_in[4];
    const float* sp_o1   = (const float*)d_in[5];
    const float* sp_w2   = (const float*)d_in[6];
    const float* sp_b2   = (const float*)d_in[7];
    const float* sp_s2   = (const float*)d_in[8];
    const float* sp_o2   = (const float*)d_in[9];
    const float* sp_w3   = (const float*)d_in[10];
    const float* sp_b3   = (const float*)d_in[11];
    const float* sp_s3   = (const float*)d_in[12];
    const float* sp_o3   = (const float*)d_in[13];
    const float* off_w   = (const float*)d_in[14];
    const float* off_b   = (const float*)d_in[15];
    const float* dcoff_w = (const float*)d_in[16];
    const float* dcoff_b = (const float*)d_in[17];
    const float* dc_w    = (const float*)d_in[18];
    const float* m_w     = (const float*)d_in[19];
    const float* m_b     = (const float*)d_in[20];
    const float* weight  = (const float*)d_in[21];
    const float* bias    = (const float*)d_in[22];

    float *h1, *h2, *h3, *feat, *off, *mask, *b36;
    uint4 *xqi, *hqi3;
    unsigned *Af, *Ah2, *Al2, *Ah3, *Al3, *Ahdc, *Aldc, *Ah36, *Al36;
    cudaGetSymbolAddress((void**)&h1,   g_h1);
    cudaGetSymbolAddress((void**)&h2,   g_h2);
    cudaGetSymbolAddress((void**)&h3,   g_h3);
    cudaGetSymbolAddress((void**)&feat, g_feat);
    cudaGetSymbolAddress((void**)&off,  g_off);
    cudaGetSymbolAddress((void**)&mask, g_mask);
    cudaGetSymbolAddress((void**)&b36,  g_b36);
    cudaGetSymbolAddress((void**)&xqi,  g_xqi);
    cudaGetSymbolAddress((void**)&hqi3, g_hqi3);
    cudaGetSymbolAddress((void**)&Af,   g_Af);
    cudaGetSymbolAddress((void**)&Ah2,  g_Ah2);
    cudaGetSymbolAddress((void**)&Al2,  g_Al2);
    cudaGetSymbolAddress((void**)&Ah3,  g_Ah3);
    cudaGetSymbolAddress((void**)&Al3,  g_Al3);
    cudaGetSymbolAddress((void**)&Ahdc, g_Ahdc);
    cudaGetSymbolAddress((void**)&Aldc, g_Aldc);
    cudaGetSymbolAddress((void**)&Ah36, g_Ah36);
    cudaGetSymbolAddress((void**)&Al36, g_Al36);

    const int SMEM_SHIFT = 2 * 3456 * 4;   // 27648 (single-f16 B, 2 bufs)
    const int SMEM_MID   = 2 * 2304 * 4;   // 18432
    cudaFuncSetAttribute(conv_shift<1>,
                         cudaFuncAttributeMaxDynamicSharedMemorySize, SMEM_SHIFT);
    cudaFuncSetAttribute(conv_shift<2>,
                         cudaFuncAttributeMaxDynamicSharedMemorySize, SMEM_SHIFT);
    cudaFuncSetAttribute(dcn_mid,
                         cudaFuncAttributeMaxDynamicSharedMemorySize, SMEM_MID);

    auto tgrid = [](int n) { return (n + 255) / 256; };
    dim3 grid(64, BATCH);

    prep_shift_f16<<<tgrid(64 * 576), 256>>>(sp_w2, Ah2, Al2, 64);                // 0
    prep_shift_f16<<<tgrid(64 * 576), 256>>>(sp_w3, Ah3, Al3, 64);                // 1
    sp1_kernel<<<grid, 256>>>(S, sp_w1, sp_b1, sp_s1, sp_o1, h1);                 // 2
    conv_shift<1><<<grid, 256, SMEM_SHIFT>>>(h1, Ah2, Al2,
                                             sp_b2, sp_s2, sp_o2, h2, 64);        // 3 <- ncu
    conv_shift<1><<<grid, 256, SMEM_SHIFT>>>(h2, Ah3, Al3,
                                             sp_b3, sp_s3, sp_o3, h3, 64);        // 4
    quad_h2i<<<tgrid(BATCH * 128 * HW), 256>>>(x, xqi, BATCH * 128 * HW, 128);    // 5
    prep_shift_w36<<<tgrid(64 * 576), 256>>>(off_w, dcoff_w, Ah36, Al36);         // 6
    concat_bias36<<<1, 36>>>(off_b, dcoff_b, b36);                                // 7
    prep_middc_tap<<<tgrid(64 * 576), 256>>>(dc_w, Ahdc, Aldc);                   // 8
    conv_shift<2><<<grid, 256, SMEM_SHIFT>>>(h3, Ah36, Al36,
                                             b36, nullptr, nullptr, off, 36);     // 9
    quad_h2i<<<tgrid(BATCH * 32 * HW), 256>>>(h3, hqi3, BATCH * 32 * HW, 32);     // 10
    dcn_mid<<<grid, 256, SMEM_MID>>>(hqi3, Ahdc, Aldc, off + 18 * HW, 36 * HW, feat); // 11
    mask_kernel<<<(BATCH * HW + 255) / 256, 256>>>(feat, m_w, m_b, mask);         // 12
    prep_final_f16<<<tgrid(256 * 2304), 256>>>(weight, Af);                       // 13
    dcn_final_f16<<<grid, 256>>>(xqi, Af, off, mask, bias, (float*)d_out);        // 14
}

// round 16
// speedup vs baseline: 1.2914x; 1.0786x over previous
#include <cuda_runtime.h>
#include <cuda_fp16.h>
#include <math.h>
#include <stdint.h>

#define HW 4096     // 64*64
#define BATCH 8

// ---------------- scratch (static device globals; no allocation) ----------------
__device__ float g_h1  [BATCH*64*HW];
__device__ float g_h2  [BATCH*64*HW];
__device__ float g_h3  [BATCH*64*HW];
__device__ float g_off [BATCH*36*HW];   // ch 0..17 = offset, 18..35 = dc_off
__device__ float g_mask[BATCH*9*HW];
__device__ float g_b36 [36];

// channel-pair-interleaved f16 quads
__device__ uint4 g_xqi [BATCH*128*HW];  // 64MB (x, 256 ch -> 128 pairs)
__device__ uint4 g_hqi3[BATCH*32*HW];   // 16MB (h3, 64 ch -> 32 pairs)

// f16 fragment-packed weights (each u32 = 2 f16 along K)
__device__ unsigned g_Af[144*16*32*4];
#define MIDA (36*4*32*4)
__device__ unsigned g_Ah2 [MIDA], g_Al2 [MIDA];   // shift-order
__device__ unsigned g_Ah3 [MIDA], g_Al3 [MIDA];   // shift-order
__device__ unsigned g_Ah36[MIDA], g_Al36[MIDA];   // shift-order
__device__ unsigned g_Ahdc[MIDA], g_Aldc[MIDA];   // tap-major (K=kk*64+c)

// ---------------- helpers ------------------------------------------------------------
__device__ __forceinline__ void mma_f16(float* acc, unsigned a0, unsigned a1,
                                        unsigned a2, unsigned a3,
                                        unsigned b0, unsigned b1) {
    asm volatile(
        "mma.sync.aligned.m16n8k16.row.col.f32.f16.f16.f32 "
        "{%0,%1,%2,%3}, {%4,%5,%6,%7}, {%8,%9}, {%0,%1,%2,%3};"
        : "+f"(acc[0]), "+f"(acc[1]), "+f"(acc[2]), "+f"(acc[3])
        : "r"(a0), "r"(a1), "r"(a2), "r"(a3), "r"(b0), "r"(b1));
}

__device__ __forceinline__ void frag_coords(int om, int kk, int& lane, int& reg, int& half) {
    int kpair = kk >> 1;
    half = kk & 1;
    lane = (om & 7) * 4 + (kpair & 3);
    reg = (om >> 3) + ((kpair >> 2) << 1);
}

__device__ __forceinline__ unsigned pack_h2(__half lo, __half hi) {
    return (unsigned)__half_as_ushort(lo) | ((unsigned)__half_as_ushort(hi) << 16);
}

__device__ __forceinline__ float dot2h(float4 w, unsigned qa, unsigned qb) {
    float2 f0 = __half22float2(*reinterpret_cast<__half2*>(&qa));
    float2 f1 = __half22float2(*reinterpret_cast<__half2*>(&qb));
    return w.x * f0.x + w.y * f0.y + w.z * f1.x + w.w * f1.y;
}

// ---------------- weight prep kernels -------------------------------------------------
__global__ void prep_middc_tap(const float* __restrict__ w, unsigned* __restrict__ hi,
                               unsigned* __restrict__ lo) {
    int i = blockIdx.x * blockDim.x + threadIdx.x;
    if (i >= 64 * 576) return;
    int K = i % 576;
    int o = i / 576;
    float v = w[o * 576 + K];
    __half vh = __float2half(v);
    __half vl = __float2half(v - __half2float(vh));
    int c = K / 9, kk = K - c * 9;
    int Kn = kk * 64 + c;
    int kc = Kn >> 4, kwi = Kn & 15;
    int lane, reg, half;
    frag_coords(o & 15, kwi, lane, reg, half);
    size_t base = ((((size_t)kc * 4 + (o >> 4)) * 32 + lane) * 4 + reg) * 2 + half;
    ((__half*)hi)[base] = vh;
    ((__half*)lo)[base] = vl;
}

__global__ void prep_shift_f16(const float* __restrict__ w, unsigned* __restrict__ hi,
                               unsigned* __restrict__ lo, int O) {
    int i = blockIdx.x * blockDim.x + threadIdx.x;
    if (i >= 64 * 576) return;
    int K = i % 576;
    int o = i / 576;
    float v = (o < O) ? w[o * 576 + K] : 0.0f;
    __half vh = __float2half(v);
    __half vl = __float2half(v - __half2float(vh));
    int c = K / 9, kk = K % 9;
    int slab = c >> 5, cl = c & 31;
    int kcg = (slab * 9 + kk) * 2 + (cl >> 4);
    int lane, reg, half;
    frag_coords(o & 15, cl & 15, lane, reg, half);
    size_t base = ((((size_t)kcg * 4 + (o >> 4)) * 32 + lane) * 4 + reg) * 2 + half;
    ((__half*)hi)[base] = vh;
    ((__half*)lo)[base] = vl;
}

__global__ void prep_shift_w36(const float* __restrict__ wa, const float* __restrict__ wb,
                               unsigned* __restrict__ hi, unsigned* __restrict__ lo) {
    int i = blockIdx.x * blockDim.x + threadIdx.x;
    if (i >= 64 * 576) return;
    int K = i % 576;
    int o = i / 576;
    float v = 0.0f;
    if (o < 18) v = wa[o * 576 + K];
    else if (o < 36) v = wb[(o - 18) * 576 + K];
    __half vh = __float2half(v);
    __half vl = __float2half(v - __half2float(vh));
    int c = K / 9, kk = K % 9;
    int slab = c >> 5, cl = c & 31;
    int kcg = (slab * 9 + kk) * 2 + (cl >> 4);
    int lane, reg, half;
    frag_coords(o & 15, cl & 15, lane, reg, half);
    size_t base = ((((size_t)kcg * 4 + (o >> 4)) * 32 + lane) * 4 + reg) * 2 + half;
    ((__half*)hi)[base] = vh;
    ((__half*)lo)[base] = vl;
}

// final: tap-major Kn = kk*256 + c
__global__ void prep_final_f16(const float* __restrict__ w, unsigned* __restrict__ dst) {
    int i = blockIdx.x * blockDim.x + threadIdx.x;
    if (i >= 256 * 2304) return;
    int K = i % 2304;
    int o = i / 2304;
    int c = K / 9, kk = K - c * 9;
    int Kn = kk * 256 + c;
    int kc = Kn >> 4, kwi = Kn & 15;
    int lane, reg, half;
    frag_coords(o & 15, kwi, lane, reg, half);
    size_t base = ((((size_t)kc * 16 + (o >> 4)) * 32 + lane) * 4 + reg) * 2 + half;
    ((__half*)dst)[base] = __float2half(w[i]);
}

__global__ void concat_bias36(const float* __restrict__ a, const float* __restrict__ b,
                              float* __restrict__ dst) {
    int i = threadIdx.x;
    if (i < 18) dst[i] = a[i];
    else if (i < 36) dst[i] = b[i - 18];
}

// ---------------- channel-pair interleaved f16 quad shingle ---------------------------
__global__ void quad_h2i(const float* __restrict__ src, uint4* __restrict__ dst,
                         int total, int C2) {
    int i = blockIdx.x * blockDim.x + threadIdx.x;
    if (i >= total) return;
    int pix = i & (HW - 1);
    int bc2 = i >> 12;
    int b = bc2 / C2;
    int c2 = bc2 - b * C2;
    int xx = pix & 63, yy = pix >> 6;
    const float* s0 = src + ((size_t)(b * 2 * C2 + c2 * 2)) * HW;
    const float* s1 = s0 + HW;
    bool okx = (xx < 63), oky = (yy < 63);
    float A0 = s0[pix];
    float B0 = okx ? s0[pix + 1] : 0.0f;
    float C0 = oky ? s0[pix + 64] : 0.0f;
    float D0 = (okx && oky) ? s0[pix + 65] : 0.0f;
    float A1 = s1[pix];
    float B1 = okx ? s1[pix + 1] : 0.0f;
    float C1 = oky ? s1[pix + 64] : 0.0f;
    float D1 = (okx && oky) ? s1[pix + 65] : 0.0f;
    dst[i] = make_uint4(pack_h2(__float2half(A0), __float2half(B0)),
                        pack_h2(__float2half(C0), __float2half(D0)),
                        pack_h2(__float2half(A1), __float2half(B1)),
                        pack_h2(__float2half(C1), __float2half(D1)));
}

// ---------------- sp1: fused resize + conv3x3 (CIN=3) + BN + ReLU, fp32 --------------
__device__ __forceinline__ float resize_at(const float* __restrict__ p, int y, int x) {
    const float scale = 127.0f / 63.0f;
    float ys = y * scale, xs = x * scale;
    float fy = floorf(ys), fx = floorf(xs);
    int y0 = (int)fy, x0 = (int)fx;
    int y1 = min(y0 + 1, 127), x1 = min(x0 + 1, 127);
    float wy = ys - fy, wx = xs - fx;
    return p[y0 * 128 + x0] * (1.0f - wy) * (1.0f - wx)
         + p[y0 * 128 + x1] * (1.0f - wy) * wx
         + p[y1 * 128 + x0] * wy * (1.0f - wx)
         + p[y1 * 128 + x1] * wy * wx;
}

__global__ void __launch_bounds__(256)
sp1_kernel(const float* __restrict__ S, const float* __restrict__ w1,
           const float* __restrict__ e_b, const float* __restrict__ e_s,
           const float* __restrict__ e_o, float* __restrict__ out) {
    __shared__ __align__(16) float s_t[576];
    const int b = blockIdx.y;
    const int tile = blockIdx.x;
    const int tid = threadIdx.x;
    const int o = tid & 63;
    const int pbase = (tid >> 6) * 16;

    float acc[16];
#pragma unroll
    for (int j = 0; j < 16; j++) acc[j] = 0.0f;

    for (int c = 0; c < 3; c++) {
        const float* Sc = S + (size_t)(b * 3 + c) * 128 * 128;
        for (int e = tid; e < 576; e += 256) {
            int k = e >> 6, p = e & 63;
            int yy = tile + k / 3 - 1;
            int xx = p + k % 3 - 1;
            s_t[e] = ((unsigned)yy < 64u && (unsigned)xx < 64u)
                         ? resize_at(Sc, yy, xx) : 0.0f;
        }
        __syncthreads();

        float wv[9];
#pragma unroll
        for (int k = 0; k < 9; k++) wv[k] = __ldg(w1 + o * 27 + c * 9 + k);

#pragma unroll
        for (int k = 0; k < 9; k++) {
            const float4* sp = reinterpret_cast<const float4*>(s_t + k * 64 + pbase);
#pragma unroll
            for (int j4 = 0; j4 < 4; j4++) {
                float4 sv = sp[j4];
                acc[j4 * 4 + 0] += wv[k] * sv.x;
                acc[j4 * 4 + 1] += wv[k] * sv.y;
                acc[j4 * 4 + 2] += wv[k] * sv.z;
                acc[j4 * 4 + 3] += wv[k] * sv.w;
            }
        }
        __syncthreads();
    }

    float bb = __ldg(e_b + o), ssc = __ldg(e_s + o), oof = __ldg(e_o + o);
    float* op = out + ((size_t)b * 64 + o) * HW + tile * 64 + pbase;
#pragma unroll
    for (int j = 0; j < 16; j++)
        op[j] = fmaxf((acc[j] + bb) * ssc + oof, 0.0f);
}

// ---------------- plain conv3x3: single-f16 B, 2-term weights, paired fill -----------
template <int EPI>
__global__ void __launch_bounds__(256)
conv_shift(const float* __restrict__ inp,
           const unsigned* __restrict__ Ahi, const unsigned* __restrict__ Alo,
           const float* __restrict__ e_b, const float* __restrict__ e_s,
           const float* __restrict__ e_o, float* __restrict__ out, int Oact) {
    extern __shared__ unsigned csm[];    // [2][3456] single-f16 B

    const int b = blockIdx.y;
    const int tile = blockIdx.x;
    const int tid = threadIdx.x;
    const int warp = tid >> 5;
    const int lane = tid & 31;
    const int mt = warp >> 1;
    const int nh = warp & 1;

    float acc[4][4];
#pragma unroll
    for (int nt = 0; nt < 4; nt++)
#pragma unroll
        for (int r = 0; r < 4; r++) acc[nt][r] = 0.0f;

    const float* xb = inp + (size_t)b * 64 * HW;

    auto fill = [&](int slab, int buf) {
        unsigned* bh = csm + buf * 3456;
        // interior: paired pixels (px, px+1) always jointly in-bounds horizontally
        for (int u = tid; u < 1536; u += 256) {
            int r = u / 512;
            int rem = u - r * 512;
            int cp = rem >> 5;
            int j = rem & 31;
            int col = 2 * j + 1;       // 1..63
            int px = col - 1;          // 0,2,..62 (8B aligned)
            int yy = tile - 1 + r;
            float2 v0 = make_float2(0.0f, 0.0f);
            float2 v1 = make_float2(0.0f, 0.0f);
            if ((unsigned)yy < 64u) {
                const float* p0 = xb + (size_t)(slab * 32 + cp * 2) * HW + yy * 64 + px;
                v0 = __ldg((const float2*)p0);
                v1 = __ldg((const float2*)(p0 + HW));
            }
            int idx = (r * 16 + cp) * 72 + col;
            bh[idx]     = pack_h2(__float2half(v0.x), __float2half(v1.x));
            bh[idx + 1] = pack_h2(__float2half(v0.y), __float2half(v1.y));
        }
        // boundary zero columns 0 and 65
        for (int e = tid; e < 96; e += 256) {
            int r = e / 32;
            int rem = e - r * 32;
            int cp = rem >> 1;
            int col = (rem & 1) ? 65 : 0;
            bh[(r * 16 + cp) * 72 + col] = 0;
        }
    };

    fill(0, 0);
    __syncthreads();

    for (int slab = 0; slab < 2; slab++) {
        if (slab == 0) fill(1, 1);
        const unsigned* sbh = csm + slab * 3456;
#pragma unroll
        for (int t = 0; t < 9; t++) {
            const int dy = t / 3, dx = t % 3;
            const unsigned* rbh = sbh + dy * 16 * 72;
#pragma unroll
            for (int kcl = 0; kcl < 2; kcl++) {
                int kcg = (slab * 9 + t) * 2 + kcl;
                uint4 Ah = __ldg((const uint4*)(Ahi + (((size_t)kcg * 4 + mt) * 32 + lane) * 4));
                uint4 Al = __ldg((const uint4*)(Alo + (((size_t)kcg * 4 + mt) * 32 + lane) * 4));
                int boff = (kcl * 8 + (lane & 3)) * 72 + (lane >> 2) + nh * 32 + dx;
                const unsigned* bh = rbh + boff;
#pragma unroll
                for (int nt = 0; nt < 4; nt++) {
                    unsigned b0h = bh[nt * 8], b1h = bh[nt * 8 + 4 * 72];
                    mma_f16(acc[nt], Ah.x, Ah.y, Ah.z, Ah.w, b0h, b1h);
                    mma_f16(acc[nt], Al.x, Al.y, Al.z, Al.w, b0h, b1h);
                }
            }
        }
        __syncthreads();
    }

    int o = mt * 16 + (lane >> 2);
    float b0 = 0, s0 = 1, f0 = 0, b1 = 0, s1 = 1, f1 = 0;
    if (EPI == 1) {
        if (o < Oact)     { b0 = __ldg(e_b + o);     s0 = __ldg(e_s + o);     f0 = __ldg(e_o + o); }
        if (o + 8 < Oact) { b1 = __ldg(e_b + o + 8); s1 = __ldg(e_s + o + 8); f1 = __ldg(e_o + o + 8); }
    } else if (EPI == 2) {
        if (o < Oact)     b0 = __ldg(e_b + o);
        if (o + 8 < Oact) b1 = __ldg(e_b + o + 8);
    }
    int colb = tile * 64 + nh * 32 + (lane & 3) * 2;
    float* o0 = out + ((size_t)b * Oact + o) * HW + colb;
    float* o1 = o0 + 8 * HW;
#pragma unroll
    for (int nt = 0; nt < 4; nt++) {
        float v0a = acc[nt][0], v0b = acc[nt][1];
        float v1a = acc[nt][2], v1b = acc[nt][3];
        if (EPI == 1) {
            v0a = fmaxf((v0a + b0) * s0 + f0, 0.0f);
            v0b = fmaxf((v0b + b0) * s0 + f0, 0.0f);
            v1a = fmaxf((v1a + b1) * s1 + f1, 0.0f);
            v1b = fmaxf((v1b + b1) * s1 + f1, 0.0f);
        } else if (EPI == 2) {
            v0a += b0; v0b += b0; v1a += b1; v1b += b1;
        }
        if (o < Oact)
            *reinterpret_cast<float2*>(o0 + nt * 8) = make_float2(v0a, v0b);
        if (o + 8 < Oact)
            *reinterpret_cast<float2*>(o1 + nt * 8) = make_float2(v1a, v1b);
    }
}

// ---------------- deform table build: 1 int + 1 float4 -------------------------------
template <bool MASKED>
__device__ __forceinline__ void build_tables(
    int tid, int tile, int b, const float* __restrict__ offs, int offBS,
    const float* __restrict__ msk, int* s_ii, float4* s_ww) {
    for (int e = tid; e < 576; e += 256) {
        int k = e >> 6, p = e & 63;
        int pix = tile * 64 + p;
        float py = (float)(tile - 1 + k / 3)
                 + offs[(size_t)b * offBS + (2 * k) * HW + pix];
        float px = (float)(p - 1 + k % 3)
                 + offs[(size_t)b * offBS + (2 * k + 1) * HW + pix];
        float m = MASKED ? msk[(size_t)b * 9 * HW + k * HW + pix] : 1.0f;
        float fy = floorf(py), fx = floorf(px);
        int iy = (int)fy, ix = (int)fx;
        float ay = py - fy, ax = px - fx;
        bool vy0 = (iy >= 0) && (iy < 64);
        bool vy1 = (iy >= -1) && (iy < 63);
        bool vx0 = (ix >= 0) && (ix < 64);
        bool vx1 = (ix >= -1) && (ix < 63);
        int yb = min(max(iy, 0), 62), xb = min(max(ix, 0), 62);
        float wAx = 0.0f, wBx = 0.0f;
        if (vx0) { if (min(max(ix, 0), 63) == xb) wAx += 1.0f - ax; else wBx += 1.0f - ax; }
        if (vx1) { if (min(max(ix + 1, 0), 63) == xb) wAx += ax; else wBx += ax; }
        float wy0 = 0.0f, wy1 = 0.0f;
        if (vy0) { if (min(max(iy, 0), 63) == yb) wy0 += 1.0f - ay; else wy1 += 1.0f - ay; }
        if (vy1) { if (min(max(iy + 1, 0), 63) == yb) wy0 += ay; else wy1 += ay; }
        wy0 *= m; wy1 *= m;
        s_ii[e] = yb * 64 + xb;
        s_ww[e] = make_float4(wy0 * wAx, wy0 * wBx, wy1 * wAx, wy1 * wBx);
    }
}

// ---------------- DCNv1 mid conv + fused 1x1 mask conv + sigmoid ---------------------
__global__ void __launch_bounds__(256)
dcn_mid(const uint4* __restrict__ hq,
        const unsigned* __restrict__ Ahi, const unsigned* __restrict__ Alo,
        const float* __restrict__ offs, int offBS,
        const float* __restrict__ mw, const float* __restrict__ mb,
        float* __restrict__ mask) {
    extern __shared__ unsigned msm[];    // [2][2304]; reused as feat tile in epilogue
    __shared__ int s_ii[576];
    __shared__ float4 s_ww[576];

    const int b = blockIdx.y;
    const int tile = blockIdx.x;
    const int tid = threadIdx.x;
    const int warp = tid >> 5;
    const int lane = tid & 31;
    const int mt = warp >> 1;
    const int nh = warp & 1;
    const int q = lane >> 2;

    build_tables<false>(tid, tile, b, offs, offBS, nullptr, s_ii, s_ww);
    __syncthreads();

    float acc[4][4];
#pragma unroll
    for (int nt = 0; nt < 4; nt++)
#pragma unroll
        for (int r = 0; r < 4; r++) acc[nt][r] = 0.0f;

    const int p = tid & 63;
    const int jp0 = tid >> 6;
    const int perm = (p & 7) * 8 + (p >> 3);

    auto gather = [&](int slab, int buf) {
        unsigned* bh = msm + buf * 2304;
        int r = slab * 64 + p;              // slab == tap
        int ib = s_ii[r];
        float4 w4 = s_ww[r];
        const uint4* xc = hq + ((size_t)b * 32 + jp0) * HW;
        int jp = jp0;
#pragma unroll
        for (int i = 0; i < 8; i++) {
            uint4 Q = __ldg(xc + ib);
            float va = dot2h(w4, Q.x, Q.y);
            float vb = dot2h(w4, Q.z, Q.w);
            bh[jp * 72 + perm] = pack_h2(__float2half(va), __float2half(vb));
            jp += 4;
            xc += 4 * HW;
        }
    };

    gather(0, 0);
    __syncthreads();

    for (int slab = 0; slab < 9; slab++) {
        if (slab < 8) gather(slab + 1, (slab + 1) & 1);
        const unsigned* sbh = msm + (slab & 1) * 2304;
#pragma unroll
        for (int kc = 0; kc < 4; kc++) {
            int kcg = slab * 4 + kc;
            uint4 Ah = __ldg((const uint4*)(Ahi + (((size_t)kcg * 4 + mt) * 32 + lane) * 4));
            uint4 Al = __ldg((const uint4*)(Alo + (((size_t)kcg * 4 + mt) * 32 + lane) * 4));
            int boff = (kc * 8 + (lane & 3)) * 72 + q * 8 + nh * 4;
            uint4 B0h = *(const uint4*)(sbh + boff);
            uint4 B1h = *(const uint4*)(sbh + boff + 4 * 72);
            mma_f16(acc[0], Ah.x, Ah.y, Ah.z, Ah.w, B0h.x, B1h.x);
            mma_f16(acc[0], Al.x, Al.y, Al.z, Al.w, B0h.x, B1h.x);
            mma_f16(acc[1], Ah.x, Ah.y, Ah.z, Ah.w, B0h.y, B1h.y);
            mma_f16(acc[1], Al.x, Al.y, Al.z, Al.w, B0h.y, B1h.y);
            mma_f16(acc[2], Ah.x, Ah.y, Ah.z, Ah.w, B0h.z, B1h.z);
            mma_f16(acc[2], Al.x, Al.y, Al.z, Al.w, B0h.z, B1h.z);
            mma_f16(acc[3], Ah.x, Ah.y, Ah.z, Ah.w, B0h.w, B1h.w);
            mma_f16(acc[3], Al.x, Al.y, Al.z, Al.w, B0h.w, B1h.w);
        }
        __syncthreads();
    }

    // ---- fused epilogue: stage feat in SMEM (pitch 65), compute mask in-block ----
    float* s_feat = (float*)msm;   // 64*65*4 = 16640 B <= 18432 B
    {
        int o = mt * 16 + (lane >> 2);
        int pxb = nh * 32 + (lane & 3) * 2;
#pragma unroll
        for (int nt = 0; nt < 4; nt++) {
            int px = pxb + nt * 8;
            s_feat[o * 65 + px]           = acc[nt][0];
            s_feat[o * 65 + px + 1]       = acc[nt][1];
            s_feat[(o + 8) * 65 + px]     = acc[nt][2];
            s_feat[(o + 8) * 65 + px + 1] = acc[nt][3];
        }
    }
    __syncthreads();

    for (int e = tid; e < 576; e += 256) {
        int k = e >> 6, pp = e & 63;
        float a = __ldg(mb + k);
        const float* wrow = mw + k * 64;
#pragma unroll 8
        for (int c = 0; c < 64; c++)
            a += s_feat[c * 65 + pp] * __ldg(wrow + c);
        mask[((size_t)b * 9 + k) * HW + tile * 64 + pp] = 1.0f / (1.0f + expf(-a));
    }
}

// ---------------- final modulated DCNv2: interleaved-pair quad gather ----------------
__global__ void __launch_bounds__(256)
dcn_final_f16(const uint4* __restrict__ xq, const unsigned* __restrict__ Af,
              const float* __restrict__ offs, const float* __restrict__ msk,
              const float* __restrict__ bias, float* __restrict__ out) {
    __shared__ unsigned s_bA[2][32 * 72];
    __shared__ int s_ii[576];
    __shared__ float4 s_ww[576];

    const int b = blockIdx.y;
    const int tile = blockIdx.x;
    const int tid = threadIdx.x;
    const int warp = tid >> 5;
    const int lane = tid & 31;
    const int q = lane >> 2;

    build_tables<true>(tid, tile, b, offs, 36 * HW, msk, s_ii, s_ww);
    __syncthreads();

    float acc[2][8][4];
#pragma unroll
    for (int mtl = 0; mtl < 2; mtl++)
#pragma unroll
        for (int nt = 0; nt < 8; nt++)
#pragma unroll
            for (int r = 0; r < 4; r++) acc[mtl][nt][r] = 0.0f;

    const int p = tid & 63;
    const int jp0 = tid >> 6;
    const int perm = (p & 7) * 8 + (p >> 3);

    auto gather = [&](int slab, int buf) {
        unsigned* bdst = s_bA[buf];
        int kk = slab >> 2;
        int r = kk * 64 + p;
        int ib = s_ii[r];
        float4 w4 = s_ww[r];
        const uint4* xc = xq + ((size_t)b * 128 + (slab & 3) * 32 + jp0) * HW;
        int jp = jp0;
#pragma unroll
        for (int i = 0; i < 8; i++) {
            uint4 Q = __ldg(xc + ib);
            float va = dot2h(w4, Q.x, Q.y);
            float vb = dot2h(w4, Q.z, Q.w);
            bdst[jp * 72 + perm] = pack_h2(__float2half(va), __float2half(vb));
            jp += 4;
            xc += 4 * HW;
        }
    };

    gather(0, 0);
    __syncthreads();

    for (int slab = 0; slab < 36; slab++) {
        if (slab < 35) gather(slab + 1, (slab + 1) & 1);
        const unsigned* sb = s_bA[slab & 1];
#pragma unroll
        for (int kc = 0; kc < 4; kc++) {
            int kcg = slab * 4 + kc;
            const unsigned* ap = Af + (((size_t)kcg * 16 + warp * 2) * 32 + lane) * 4;
            uint4 A0 = __ldg((const uint4*)ap);
            uint4 A1 = __ldg((const uint4*)(ap + 128));

            int boff = (kc * 8 + (lane & 3)) * 72 + q * 8;
            uint4 B0a = *(const uint4*)(sb + boff);
            uint4 B0b = *(const uint4*)(sb + boff + 4);
            uint4 B1a = *(const uint4*)(sb + boff + 4 * 72);
            uint4 B1b = *(const uint4*)(sb + boff + 4 * 72 + 4);
            mma_f16(acc[0][0], A0.x, A0.y, A0.z, A0.w, B0a.x, B1a.x);
            mma_f16(acc[1][0], A1.x, A1.y, A1.z, A1.w, B0a.x, B1a.x);
            mma_f16(acc[0][1], A0.x, A0.y, A0.z, A0.w, B0a.y, B1a.y);
            mma_f16(acc[1][1], A1.x, A1.y, A1.z, A1.w, B0a.y, B1a.y);
            mma_f16(acc[0][2], A0.x, A0.y, A0.z, A0.w, B0a.z, B1a.z);
            mma_f16(acc[1][2], A1.x, A1.y, A1.z, A1.w, B0a.z, B1a.z);
            mma_f16(acc[0][3], A0.x, A0.y, A0.z, A0.w, B0a.w, B1a.w);
            mma_f16(acc[1][3], A1.x, A1.y, A1.z, A1.w, B0a.w, B1a.w);
            mma_f16(acc[0][4], A0.x, A0.y, A0.z, A0.w, B0b.x, B1b.x);
            mma_f16(acc[1][4], A1.x, A1.y, A1.z, A1.w, B0b.x, B1b.x);
            mma_f16(acc[0][5], A0.x, A0.y, A0.z, A0.w, B0b.y, B1b.y);
            mma_f16(acc[1][5], A1.x, A1.y, A1.z, A1.w, B0b.y, B1b.y);
            mma_f16(acc[0][6], A0.x, A0.y, A0.z, A0.w, B0b.z, B1b.z);
            mma_f16(acc[1][6], A1.x, A1.y, A1.z, A1.w, B0b.z, B1b.z);
            mma_f16(acc[0][7], A0.x, A0.y, A0.z, A0.w, B0b.w, B1b.w);
            mma_f16(acc[1][7], A1.x, A1.y, A1.z, A1.w, B0b.w, B1b.w);
        }
        __syncthreads();
    }

#pragma unroll
    for (int mtl = 0; mtl < 2; mtl++) {
        int o = warp * 32 + mtl * 16 + (lane >> 2);
        float b_lo = __ldg(bias + o);
        float b_hi = __ldg(bias + o + 8);
        float* o0 = out + ((size_t)b * 256 + o) * HW + tile * 64 + (lane & 3) * 2;
        float* o1 = o0 + 8 * HW;
#pragma unroll
        for (int nt = 0; nt < 8; nt++) {
            *reinterpret_cast<float2*>(o0 + nt * 8) =
                make_float2(acc[mtl][nt][0] + b_lo, acc[mtl][nt][1] + b_lo);
            *reinterpret_cast<float2*>(o1 + nt * 8) =
                make_float2(acc[mtl][nt][2] + b_hi, acc[mtl][nt][3] + b_hi);
        }
    }
}

// ---------------- host launcher ------------------------------------------------------
extern "C" void kernel_launch(void* const* d_in, const int* in_sizes, int n_in,
                              void* d_out, int out_size) {
    const float* x       = (const float*)d_in[0];
    const float* S       = (const float*)d_in[1];
    const float* sp_w1   = (const float*)d_in[2];
    const float* sp_b1   = (const float*)d_in[3];
    const float* sp_s1   = (const float*)d_in[4];
    const float* sp_o1   = (const float*)d_in[5];
    const float* sp_w2   = (const float*)d_in[6];
    const float* sp_b2   = (const float*)d_in[7];
    const float* sp_s2   = (const float*)d_in[8];
    const float* sp_o2   = (const float*)d_in[9];
    const float* sp_w3   = (const float*)d_in[10];
    const float* sp_b3   = (const float*)d_in[11];
    const float* sp_s3   = (const float*)d_in[12];
    const float* sp_o3   = (const float*)d_in[13];
    const float* off_w   = (const float*)d_in[14];
    const float* off_b   = (const float*)d_in[15];
    const float* dcoff_w = (const float*)d_in[16];
    const float* dcoff_b = (const float*)d_in[17];
    const float* dc_w    = (const float*)d_in[18];
    const float* m_w     = (const float*)d_in[19];
    const float* m_b     = (const float*)d_in[20];
    const float* weight  = (const float*)d_in[21];
    const float* bias    = (const float*)d_in[22];

    float *h1, *h2, *h3, *off, *mask, *b36;
    uint4 *xqi, *hqi3;
    unsigned *Af, *Ah2, *Al2, *Ah3, *Al3, *Ahdc, *Aldc, *Ah36, *Al36;
    cudaGetSymbolAddress((void**)&h1,   g_h1);
    cudaGetSymbolAddress((void**)&h2,   g_h2);
    cudaGetSymbolAddress((void**)&h3,   g_h3);
    cudaGetSymbolAddress((void**)&off,  g_off);
    cudaGetSymbolAddress((void**)&mask, g_mask);
    cudaGetSymbolAddress((void**)&b36,  g_b36);
    cudaGetSymbolAddress((void**)&xqi,  g_xqi);
    cudaGetSymbolAddress((void**)&hqi3, g_hqi3);
    cudaGetSymbolAddress((void**)&Af,   g_Af);
    cudaGetSymbolAddress((void**)&Ah2,  g_Ah2);
    cudaGetSymbolAddress((void**)&Al2,  g_Al2);
    cudaGetSymbolAddress((void**)&Ah3,  g_Ah3);
    cudaGetSymbolAddress((void**)&Al3,  g_Al3);
    cudaGetSymbolAddress((void**)&Ahdc, g_Ahdc);
    cudaGetSymbolAddress((void**)&Aldc, g_Aldc);
    cudaGetSymbolAddress((void**)&Ah36, g_Ah36);
    cudaGetSymbolAddress((void**)&Al36, g_Al36);

    const int SMEM_SHIFT = 2 * 3456 * 4;   // 27648
    const int SMEM_MID   = 2 * 2304 * 4;   // 18432 (>= 64*65*4 feat tile)
    cudaFuncSetAttribute(conv_shift<1>,
                         cudaFuncAttributeMaxDynamicSharedMemorySize, SMEM_SHIFT);
    cudaFuncSetAttribute(conv_shift<2>,
                         cudaFuncAttributeMaxDynamicSharedMemorySize, SMEM_SHIFT);
    cudaFuncSetAttribute(dcn_mid,
                         cudaFuncAttributeMaxDynamicSharedMemorySize, SMEM_MID);

    auto tgrid = [](int n) { return (n + 255) / 256; };
    dim3 grid(64, BATCH);

    prep_shift_f16<<<tgrid(64 * 576), 256>>>(sp_w2, Ah2, Al2, 64);                // 0
    prep_shift_f16<<<tgrid(64 * 576), 256>>>(sp_w3, Ah3, Al3, 64);                // 1
    sp1_kernel<<<grid, 256>>>(S, sp_w1, sp_b1, sp_s1, sp_o1, h1);                 // 2
    conv_shift<1><<<grid, 256, SMEM_SHIFT>>>(h1, Ah2, Al2,
                                             sp_b2, sp_s2, sp_o2, h2, 64);        // 3 <- ncu
    conv_shift<1><<<grid, 256, SMEM_SHIFT>>>(h2, Ah3, Al3,
                                             sp_b3, sp_s3, sp_o3, h3, 64);        // 4
    quad_h2i<<<tgrid(BATCH * 128 * HW), 256>>>(x, xqi, BATCH * 128 * HW, 128);    // 5
    prep_shift_w36<<<tgrid(64 * 576), 256>>>(off_w, dcoff_w, Ah36, Al36);         // 6
    concat_bias36<<<1, 36>>>(off_b, dcoff_b, b36);                                // 7
    prep_middc_tap<<<tgrid(64 * 576), 256>>>(dc_w, Ahdc, Aldc);                   // 8
    conv_shift<2><<<grid, 256, SMEM_SHIFT>>>(h3, Ah36, Al36,
                                             b36, nullptr, nullptr, off, 36);     // 9
    quad_h2i<<<tgrid(BATCH * 32 * HW), 256>>>(h3, hqi3, BATCH * 32 * HW, 32);     // 10
    dcn_mid<<<grid, 256, SMEM_MID>>>(hqi3, Ahdc, Aldc, off + 18 * HW, 36 * HW,
                                     m_w, m_b, mask);                             // 11
    prep_final_f16<<<tgrid(256 * 2304), 256>>>(weight, Af);                       // 12
    dcn_final_f16<<<grid, 256>>>(xqi, Af, off, mask, bias, (float*)d_out);        // 13
}

// round 17
// speedup vs baseline: 1.3358x; 1.0344x over previous
#include <cuda_runtime.h>
#include <cuda_fp16.h>
#include <math.h>
#include <stdint.h>

#define HW 4096     // 64*64
#define BATCH 8

// ---------------- scratch (static device globals; no allocation) ----------------
__device__ float g_h1  [BATCH*64*HW];
__device__ float g_h2  [BATCH*64*HW];
__device__ float g_h3  [BATCH*64*HW];
__device__ float g_off [BATCH*36*HW];   // ch 0..17 = offset, 18..35 = dc_off
__device__ float g_mask[BATCH*9*HW];
__device__ float g_b36 [36];

// channel-pair-interleaved f16 quads
__device__ uint4 g_xqi [BATCH*128*HW];  // 64MB
__device__ uint4 g_hqi3[BATCH*32*HW];   // 16MB

// f16 fragment-packed weights (each u32 = 2 f16 along K)
__device__ unsigned g_Af[144*16*32*4];
#define MIDA (36*4*32*4)
__device__ unsigned g_Ah2 [MIDA], g_Al2 [MIDA];
__device__ unsigned g_Ah3 [MIDA], g_Al3 [MIDA];
__device__ unsigned g_Ah36[MIDA], g_Al36[MIDA];
__device__ unsigned g_Ahdc[MIDA], g_Aldc[MIDA];

// ---------------- helpers ------------------------------------------------------------
__device__ __forceinline__ void mma_f16(float* acc, unsigned a0, unsigned a1,
                                        unsigned a2, unsigned a3,
                                        unsigned b0, unsigned b1) {
    asm volatile(
        "mma.sync.aligned.m16n8k16.row.col.f32.f16.f16.f32 "
        "{%0,%1,%2,%3}, {%4,%5,%6,%7}, {%8,%9}, {%0,%1,%2,%3};"
        : "+f"(acc[0]), "+f"(acc[1]), "+f"(acc[2]), "+f"(acc[3])
        : "r"(a0), "r"(a1), "r"(a2), "r"(a3), "r"(b0), "r"(b1));
}

__device__ __forceinline__ void frag_coords(int om, int kk, int& lane, int& reg, int& half) {
    int kpair = kk >> 1;
    half = kk & 1;
    lane = (om & 7) * 4 + (kpair & 3);
    reg = (om >> 3) + ((kpair >> 2) << 1);
}

__device__ __forceinline__ unsigned pack_h2(__half lo, __half hi) {
    return (unsigned)__half_as_ushort(lo) | ((unsigned)__half_as_ushort(hi) << 16);
}

__device__ __forceinline__ float dot2h(float4 w, unsigned qa, unsigned qb) {
    float2 f0 = __half22float2(*reinterpret_cast<__half2*>(&qa));
    float2 f1 = __half22float2(*reinterpret_cast<__half2*>(&qb));
    return w.x * f0.x + w.y * f0.y + w.z * f1.x + w.w * f1.y;
}

// ---------------- device-side task bodies (shared by mega kernel) --------------------
__device__ __forceinline__ void task_prep_shift(const float* __restrict__ w,
                                                unsigned* hi, unsigned* lo, int O, int i) {
    if (i >= 64 * 576) return;
    int K = i % 576;
    int o = i / 576;
    float v = (o < O) ? w[o * 576 + K] : 0.0f;
    __half vh = __float2half(v);
    __half vl = __float2half(v - __half2float(vh));
    int c = K / 9, kk = K % 9;
    int slab = c >> 5, cl = c & 31;
    int kcg = (slab * 9 + kk) * 2 + (cl >> 4);
    int lane, reg, half;
    frag_coords(o & 15, cl & 15, lane, reg, half);
    size_t base = ((((size_t)kcg * 4 + (o >> 4)) * 32 + lane) * 4 + reg) * 2 + half;
    ((__half*)hi)[base] = vh;
    ((__half*)lo)[base] = vl;
}

__device__ __forceinline__ void task_prep_w36(const float* __restrict__ wa,
                                              const float* __restrict__ wb,
                                              unsigned* hi, unsigned* lo, int i) {
    if (i >= 64 * 576) return;
    int K = i % 576;
    int o = i / 576;
    float v = 0.0f;
    if (o < 18) v = wa[o * 576 + K];
    else if (o < 36) v = wb[(o - 18) * 576 + K];
    __half vh = __float2half(v);
    __half vl = __float2half(v - __half2float(vh));
    int c = K / 9, kk = K % 9;
    int slab = c >> 5, cl = c & 31;
    int kcg = (slab * 9 + kk) * 2 + (cl >> 4);
    int lane, reg, half;
    frag_coords(o & 15, cl & 15, lane, reg, half);
    size_t base = ((((size_t)kcg * 4 + (o >> 4)) * 32 + lane) * 4 + reg) * 2 + half;
    ((__half*)hi)[base] = vh;
    ((__half*)lo)[base] = vl;
}

__device__ __forceinline__ void task_prep_middc(const float* __restrict__ w,
                                                unsigned* hi, unsigned* lo, int i) {
    if (i >= 64 * 576) return;
    int K = i % 576;
    int o = i / 576;
    float v = w[o * 576 + K];
    __half vh = __float2half(v);
    __half vl = __float2half(v - __half2float(vh));
    int c = K / 9, kk = K - c * 9;
    int Kn = kk * 64 + c;
    int kc = Kn >> 4, kwi = Kn & 15;
    int lane, reg, half;
    frag_coords(o & 15, kwi, lane, reg, half);
    size_t base = ((((size_t)kc * 4 + (o >> 4)) * 32 + lane) * 4 + reg) * 2 + half;
    ((__half*)hi)[base] = vh;
    ((__half*)lo)[base] = vl;
}

__device__ __forceinline__ void task_prep_final(const float* __restrict__ w,
                                                unsigned* dst, int i) {
    if (i >= 256 * 2304) return;
    int K = i % 2304;
    int o = i / 2304;
    int c = K / 9, kk = K - c * 9;
    int Kn = kk * 256 + c;
    int kc = Kn >> 4, kwi = Kn & 15;
    int lane, reg, half;
    frag_coords(o & 15, kwi, lane, reg, half);
    size_t base = ((((size_t)kc * 16 + (o >> 4)) * 32 + lane) * 4 + reg) * 2 + half;
    ((__half*)dst)[base] = __float2half(w[i]);
}

__device__ __forceinline__ void task_quad(const float* __restrict__ src,
                                          uint4* __restrict__ dst, int i, int C2) {
    int pix = i & (HW - 1);
    int bc2 = i >> 12;
    int b = bc2 / C2;
    int c2 = bc2 - b * C2;
    int xx = pix & 63, yy = pix >> 6;
    const float* s0 = src + ((size_t)(b * 2 * C2 + c2 * 2)) * HW;
    const float* s1 = s0 + HW;
    bool okx = (xx < 63), oky = (yy < 63);
    float A0 = s0[pix];
    float B0 = okx ? s0[pix + 1] : 0.0f;
    float C0 = oky ? s0[pix + 64] : 0.0f;
    float D0 = (okx && oky) ? s0[pix + 65] : 0.0f;
    float A1 = s1[pix];
    float B1 = okx ? s1[pix + 1] : 0.0f;
    float C1 = oky ? s1[pix + 64] : 0.0f;
    float D1 = (okx && oky) ? s1[pix + 65] : 0.0f;
    dst[i] = make_uint4(pack_h2(__float2half(A0), __float2half(B0)),
                        pack_h2(__float2half(C0), __float2half(D0)),
                        pack_h2(__float2half(A1), __float2half(B1)),
                        pack_h2(__float2half(C1), __float2half(D1)));
}

__device__ __forceinline__ float resize_at(const float* __restrict__ p, int y, int x) {
    const float scale = 127.0f / 63.0f;
    float ys = y * scale, xs = x * scale;
    float fy = floorf(ys), fx = floorf(xs);
    int y0 = (int)fy, x0 = (int)fx;
    int y1 = min(y0 + 1, 127), x1 = min(x0 + 1, 127);
    float wy = ys - fy, wx = xs - fx;
    return p[y0 * 128 + x0] * (1.0f - wy) * (1.0f - wx)
         + p[y0 * 128 + x1] * (1.0f - wy) * wx
         + p[y1 * 128 + x0] * wy * (1.0f - wx)
         + p[y1 * 128 + x1] * wy * wx;
}

__device__ void task_sp1(const float* __restrict__ S, const float* __restrict__ w1,
                         const float* __restrict__ e_b, const float* __restrict__ e_s,
                         const float* __restrict__ e_o, float* __restrict__ out,
                         int b, int tile, float* s_t) {
    const int tid = threadIdx.x;
    const int o = tid & 63;
    const int pbase = (tid >> 6) * 16;

    float acc[16];
#pragma unroll
    for (int j = 0; j < 16; j++) acc[j] = 0.0f;

    for (int c = 0; c < 3; c++) {
        const float* Sc = S + (size_t)(b * 3 + c) * 128 * 128;
        for (int e = tid; e < 576; e += 256) {
            int k = e >> 6, p = e & 63;
            int yy = tile + k / 3 - 1;
            int xx = p + k % 3 - 1;
            s_t[e] = ((unsigned)yy < 64u && (unsigned)xx < 64u)
                         ? resize_at(Sc, yy, xx) : 0.0f;
        }
        __syncthreads();

        float wv[9];
#pragma unroll
        for (int k = 0; k < 9; k++) wv[k] = __ldg(w1 + o * 27 + c * 9 + k);

#pragma unroll
        for (int k = 0; k < 9; k++) {
            const float4* sp = reinterpret_cast<const float4*>(s_t + k * 64 + pbase);
#pragma unroll
            for (int j4 = 0; j4 < 4; j4++) {
                float4 sv = sp[j4];
                acc[j4 * 4 + 0] += wv[k] * sv.x;
                acc[j4 * 4 + 1] += wv[k] * sv.y;
                acc[j4 * 4 + 2] += wv[k] * sv.z;
                acc[j4 * 4 + 3] += wv[k] * sv.w;
            }
        }
        __syncthreads();
    }

    float bb = __ldg(e_b + o), ssc = __ldg(e_s + o), oof = __ldg(e_o + o);
    float* op = out + ((size_t)b * 64 + o) * HW + tile * 64 + pbase;
#pragma unroll
    for (int j = 0; j < 16; j++)
        op[j] = fmaxf((acc[j] + bb) * ssc + oof, 0.0f);
}

// ---------------- mega prep kernel: sp1 + quad_x + all weight preps ------------------
// block ranges: [0,512) sp1; [512,16896) quad_x; then 4x144 prep; 2304 final; 1 bias.
__global__ void __launch_bounds__(256)
prep_mega(const float* __restrict__ S, const float* __restrict__ sp_w1,
          const float* __restrict__ sp_b1, const float* __restrict__ sp_s1,
          const float* __restrict__ sp_o1, float* __restrict__ h1,
          const float* __restrict__ x, uint4* __restrict__ xqi,
          const float* __restrict__ sp_w2, unsigned* Ah2, unsigned* Al2,
          const float* __restrict__ sp_w3, unsigned* Ah3, unsigned* Al3,
          const float* __restrict__ off_w, const float* __restrict__ dcoff_w,
          unsigned* Ah36, unsigned* Al36,
          const float* __restrict__ dc_w, unsigned* Ahdc, unsigned* Aldc,
          const float* __restrict__ weight, unsigned* Af,
          const float* __restrict__ off_b, const float* __restrict__ dcoff_b,
          float* __restrict__ b36) {
    __shared__ __align__(16) float s_t[576];
    const int blk = blockIdx.x;
    const int tid = threadIdx.x;

    if (blk < 512) {
        task_sp1(S, sp_w1, sp_b1, sp_s1, sp_o1, h1, blk >> 6, blk & 63, s_t);
    } else if (blk < 16896) {
        int i = (blk - 512) * 256 + tid;
        if (i < BATCH * 128 * HW) task_quad(x, xqi, i, 128);
    } else if (blk < 17040) {
        task_prep_shift(sp_w2, Ah2, Al2, 64, (blk - 16896) * 256 + tid);
    } else if (blk < 17184) {
        task_prep_shift(sp_w3, Ah3, Al3, 64, (blk - 17040) * 256 + tid);
    } else if (blk < 17328) {
        task_prep_w36(off_w, dcoff_w, Ah36, Al36, (blk - 17184) * 256 + tid);
    } else if (blk < 17472) {
        task_prep_middc(dc_w, Ahdc, Aldc, (blk - 17328) * 256 + tid);
    } else if (blk < 19776) {
        task_prep_final(weight, Af, (blk - 17472) * 256 + tid);
    } else {
        if (tid < 18) b36[tid] = off_b[tid];
        else if (tid < 36) b36[tid] = dcoff_b[tid - 18];
    }
}

// ---------------- quad shingle for h3 (post-sp3) --------------------------------------
__global__ void quad_h2i(const float* __restrict__ src, uint4* __restrict__ dst,
                         int total, int C2) {
    int i = blockIdx.x * blockDim.x + threadIdx.x;
    if (i >= total) return;
    task_quad(src, dst, i, C2);
}

// ---------------- plain conv3x3: single-f16 B, 2-term weights, paired fill -----------
template <int EPI>
__global__ void __launch_bounds__(256)
conv_shift(const float* __restrict__ inp,
           const unsigned* __restrict__ Ahi, const unsigned* __restrict__ Alo,
           const float* __restrict__ e_b, const float* __restrict__ e_s,
           const float* __restrict__ e_o, float* __restrict__ out, int Oact) {
    extern __shared__ unsigned csm[];    // [2][3456]

    const int b = blockIdx.y;
    const int tile = blockIdx.x;
    const int tid = threadIdx.x;
    const int warp = tid >> 5;
    const int lane = tid & 31;
    const int mt = warp >> 1;
    const int nh = warp & 1;

    float acc[4][4];
#pragma unroll
    for (int nt = 0; nt < 4; nt++)
#pragma unroll
        for (int r = 0; r < 4; r++) acc[nt][r] = 0.0f;

    const float* xb = inp + (size_t)b * 64 * HW;

    auto fill = [&](int slab, int buf) {
        unsigned* bh = csm + buf * 3456;
        for (int u = tid; u < 1536; u += 256) {
            int r = u / 512;
            int rem = u - r * 512;
            int cp = rem >> 5;
            int j = rem & 31;
            int col = 2 * j + 1;
            int px = col - 1;
            int yy = tile - 1 + r;
            float2 v0 = make_float2(0.0f, 0.0f);
            float2 v1 = make_float2(0.0f, 0.0f);
            if ((unsigned)yy < 64u) {
                const float* p0 = xb + (size_t)(slab * 32 + cp * 2) * HW + yy * 64 + px;
                v0 = __ldg((const float2*)p0);
                v1 = __ldg((const float2*)(p0 + HW));
            }
            int idx = (r * 16 + cp) * 72 + col;
            bh[idx]     = pack_h2(__float2half(v0.x), __float2half(v1.x));
            bh[idx + 1] = pack_h2(__float2half(v0.y), __float2half(v1.y));
        }
        for (int e = tid; e < 96; e += 256) {
            int r = e / 32;
            int rem = e - r * 32;
            int cp = rem >> 1;
            int col = (rem & 1) ? 65 : 0;
            bh[(r * 16 + cp) * 72 + col] = 0;
        }
    };

    fill(0, 0);
    __syncthreads();

    for (int slab = 0; slab < 2; slab++) {
        if (slab == 0) fill(1, 1);
        const unsigned* sbh = csm + slab * 3456;
#pragma unroll
        for (int t = 0; t < 9; t++) {
            const int dy = t / 3, dx = t % 3;
            const unsigned* rbh = sbh + dy * 16 * 72;
#pragma unroll
            for (int kcl = 0; kcl < 2; kcl++) {
                int kcg = (slab * 9 + t) * 2 + kcl;
                uint4 Ah = __ldg((const uint4*)(Ahi + (((size_t)kcg * 4 + mt) * 32 + lane) * 4));
                uint4 Al = __ldg((const uint4*)(Alo + (((size_t)kcg * 4 + mt) * 32 + lane) * 4));
                int boff = (kcl * 8 + (lane & 3)) * 72 + (lane >> 2) + nh * 32 + dx;
                const unsigned* bh = rbh + boff;
#pragma unroll
                for (int nt = 0; nt < 4; nt++) {
                    unsigned b0h = bh[nt * 8], b1h = bh[nt * 8 + 4 * 72];
                    mma_f16(acc[nt], Ah.x, Ah.y, Ah.z, Ah.w, b0h, b1h);
                    mma_f16(acc[nt], Al.x, Al.y, Al.z, Al.w, b0h, b1h);
                }
            }
        }
        __syncthreads();
    }

    int o = mt * 16 + (lane >> 2);
    float b0 = 0, s0 = 1, f0 = 0, b1 = 0, s1 = 1, f1 = 0;
    if (EPI == 1) {
        if (o < Oact)     { b0 = __ldg(e_b + o);     s0 = __ldg(e_s + o);     f0 = __ldg(e_o + o); }
        if (o + 8 < Oact) { b1 = __ldg(e_b + o + 8); s1 = __ldg(e_s + o + 8); f1 = __ldg(e_o + o + 8); }
    } else if (EPI == 2) {
        if (o < Oact)     b0 = __ldg(e_b + o);
        if (o + 8 < Oact) b1 = __ldg(e_b + o + 8);
    }
    int colb = tile * 64 + nh * 32 + (lane & 3) * 2;
    float* o0 = out + ((size_t)b * Oact + o) * HW + colb;
    float* o1 = o0 + 8 * HW;
#pragma unroll
    for (int nt = 0; nt < 4; nt++) {
        float v0a = acc[nt][0], v0b = acc[nt][1];
        float v1a = acc[nt][2], v1b = acc[nt][3];
        if (EPI == 1) {
            v0a = fmaxf((v0a + b0) * s0 + f0, 0.0f);
            v0b = fmaxf((v0b + b0) * s0 + f0, 0.0f);
            v1a = fmaxf((v1a + b1) * s1 + f1, 0.0f);
            v1b = fmaxf((v1b + b1) * s1 + f1, 0.0f);
        } else if (EPI == 2) {
            v0a += b0; v0b += b0; v1a += b1; v1b += b1;
        }
        if (o < Oact)
            *reinterpret_cast<float2*>(o0 + nt * 8) = make_float2(v0a, v0b);
        if (o + 8 < Oact)
            *reinterpret_cast<float2*>(o1 + nt * 8) = make_float2(v1a, v1b);
    }
}

// ---------------- deform table build: 1 int + 1 float4 -------------------------------
template <bool MASKED>
__device__ __forceinline__ void build_tables(
    int tid, int tile, int b, const float* __restrict__ offs, int offBS,
    const float* __restrict__ msk, int* s_ii, float4* s_ww) {
    for (int e = tid; e < 576; e += 256) {
        int k = e >> 6, p = e & 63;
        int pix = tile * 64 + p;
        float py = (float)(tile - 1 + k / 3)
                 + offs[(size_t)b * offBS + (2 * k) * HW + pix];
        float px = (float)(p - 1 + k % 3)
                 + offs[(size_t)b * offBS + (2 * k + 1) * HW + pix];
        float m = MASKED ? msk[(size_t)b * 9 * HW + k * HW + pix] : 1.0f;
        float fy = floorf(py), fx = floorf(px);
        int iy = (int)fy, ix = (int)fx;
        float ay = py - fy, ax = px - fx;
        bool vy0 = (iy >= 0) && (iy < 64);
        bool vy1 = (iy >= -1) && (iy < 63);
        bool vx0 = (ix >= 0) && (ix < 64);
        bool vx1 = (ix >= -1) && (ix < 63);
        int yb = min(max(iy, 0), 62), xb = min(max(ix, 0), 62);
        float wAx = 0.0f, wBx = 0.0f;
        if (vx0) { if (min(max(ix, 0), 63) == xb) wAx += 1.0f - ax; else wBx += 1.0f - ax; }
        if (vx1) { if (min(max(ix + 1, 0), 63) == xb) wAx += ax; else wBx += ax; }
        float wy0 = 0.0f, wy1 = 0.0f;
        if (vy0) { if (min(max(iy, 0), 63) == yb) wy0 += 1.0f - ay; else wy1 += 1.0f - ay; }
        if (vy1) { if (min(max(iy + 1, 0), 63) == yb) wy0 += ay; else wy1 += ay; }
        wy0 *= m; wy1 *= m;
        s_ii[e] = yb * 64 + xb;
        s_ww[e] = make_float4(wy0 * wAx, wy0 * wBx, wy1 * wAx, wy1 * wBx);
    }
}

// ---------------- DCNv1 mid conv + fused 1x1 mask conv + sigmoid ---------------------
__global__ void __launch_bounds__(256)
dcn_mid(const uint4* __restrict__ hq,
        const unsigned* __restrict__ Ahi, const unsigned* __restrict__ Alo,
        const float* __restrict__ offs, int offBS,
        const float* __restrict__ mw, const float* __restrict__ mb,
        float* __restrict__ mask) {
    extern __shared__ unsigned msm[];    // [2][2304]; reused as feat tile
    __shared__ int s_ii[576];
    __shared__ float4 s_ww[576];

    const int b = blockIdx.y;
    const int tile = blockIdx.x;
    const int tid = threadIdx.x;
    const int warp = tid >> 5;
    const int lane = tid & 31;
    const int mt = warp >> 1;
    const int nh = warp & 1;
    const int q = lane >> 2;

    build_tables<false>(tid, tile, b, offs, offBS, nullptr, s_ii, s_ww);
    __syncthreads();

    float acc[4][4];
#pragma unroll
    for (int nt = 0; nt < 4; nt++)
#pragma unroll
        for (int r = 0; r < 4; r++) acc[nt][r] = 0.0f;

    const int p = tid & 63;
    const int jp0 = tid >> 6;
    const int perm = (p & 7) * 8 + (p >> 3);

    auto gather = [&](int slab, int buf) {
        unsigned* bh = msm + buf * 2304;
        int r = slab * 64 + p;
        int ib = s_ii[r];
        float4 w4 = s_ww[r];
        const uint4* xc = hq + ((size_t)b * 32 + jp0) * HW;
        int jp = jp0;
#pragma unroll
        for (int i = 0; i < 8; i++) {
            uint4 Q = __ldg(xc + ib);
            float va = dot2h(w4, Q.x, Q.y);
            float vb = dot2h(w4, Q.z, Q.w);
            bh[jp * 72 + perm] = pack_h2(__float2half(va), __float2half(vb));
            jp += 4;
            xc += 4 * HW;
        }
    };

    gather(0, 0);
    __syncthreads();

    for (int slab = 0; slab < 9; slab++) {
        if (slab < 8) gather(slab + 1, (slab + 1) & 1);
        const unsigned* sbh = msm + (slab & 1) * 2304;
#pragma unroll
        for (int kc = 0; kc < 4; kc++) {
            int kcg = slab * 4 + kc;
            uint4 Ah = __ldg((const uint4*)(Ahi + (((size_t)kcg * 4 + mt) * 32 + lane) * 4));
            uint4 Al = __ldg((const uint4*)(Alo + (((size_t)kcg * 4 + mt) * 32 + lane) * 4));
            int boff = (kc * 8 + (lane & 3)) * 72 + q * 8 + nh * 4;
            uint4 B0h = *(const uint4*)(sbh + boff);
            uint4 B1h = *(const uint4*)(sbh + boff + 4 * 72);
            mma_f16(acc[0], Ah.x, Ah.y, Ah.z, Ah.w, B0h.x, B1h.x);
            mma_f16(acc[0], Al.x, Al.y, Al.z, Al.w, B0h.x, B1h.x);
            mma_f16(acc[1], Ah.x, Ah.y, Ah.z, Ah.w, B0h.y, B1h.y);
            mma_f16(acc[1], Al.x, Al.y, Al.z, Al.w, B0h.y, B1h.y);
            mma_f16(acc[2], Ah.x, Ah.y, Ah.z, Ah.w, B0h.z, B1h.z);
            mma_f16(acc[2], Al.x, Al.y, Al.z, Al.w, B0h.z, B1h.z);
            mma_f16(acc[3], Ah.x, Ah.y, Ah.z, Ah.w, B0h.w, B1h.w);
            mma_f16(acc[3], Al.x, Al.y, Al.z, Al.w, B0h.w, B1h.w);
        }
        __syncthreads();
    }

    float* s_feat = (float*)msm;
    {
        int o = mt * 16 + (lane >> 2);
        int pxb = nh * 32 + (lane & 3) * 2;
#pragma unroll
        for (int nt = 0; nt < 4; nt++) {
            int px = pxb + nt * 8;
            s_feat[o * 65 + px]           = acc[nt][0];
            s_feat[o * 65 + px + 1]       = acc[nt][1];
            s_feat[(o + 8) * 65 + px]     = acc[nt][2];
            s_feat[(o + 8) * 65 + px + 1] = acc[nt][3];
        }
    }
    __syncthreads();

    for (int e = tid; e < 576; e += 256) {
        int k = e >> 6, pp = e & 63;
        float a = __ldg(mb + k);
        const float* wrow = mw + k * 64;
#pragma unroll 8
        for (int c = 0; c < 64; c++)
            a += s_feat[c * 65 + pp] * __ldg(wrow + c);
        mask[((size_t)b * 9 + k) * HW + tile * 64 + pp] = 1.0f / (1.0f + expf(-a));
    }
}

// ---------------- final modulated DCNv2 ------------------------------------------------
__global__ void __launch_bounds__(256)
dcn_final_f16(const uint4* __restrict__ xq, const unsigned* __restrict__ Af,
              const float* __restrict__ offs, const float* __restrict__ msk,
              const float* __restrict__ bias, float* __restrict__ out) {
    __shared__ unsigned s_bA[2][32 * 72];
    __shared__ int s_ii[576];
    __shared__ float4 s_ww[576];

    const int b = blockIdx.y;
    const int tile = blockIdx.x;
    const int tid = threadIdx.x;
    const int warp = tid >> 5;
    const int lane = tid & 31;
    const int q = lane >> 2;

    build_tables<true>(tid, tile, b, offs, 36 * HW, msk, s_ii, s_ww);
    __syncthreads();

    float acc[2][8][4];
#pragma unroll
    for (int mtl = 0; mtl < 2; mtl++)
#pragma unroll
        for (int nt = 0; nt < 8; nt++)
#pragma unroll
            for (int r = 0; r < 4; r++) acc[mtl][nt][r] = 0.0f;

    const int p = tid & 63;
    const int jp0 = tid >> 6;
    const int perm = (p & 7) * 8 + (p >> 3);

    auto gather = [&](int slab, int buf) {
        unsigned* bdst = s_bA[buf];
        int kk = slab >> 2;
        int r = kk * 64 + p;
        int ib = s_ii[r];
        float4 w4 = s_ww[r];
        const uint4* xc = xq + ((size_t)b * 128 + (slab & 3) * 32 + jp0) * HW;
        int jp = jp0;
#pragma unroll
        for (int i = 0; i < 8; i++) {
            uint4 Q = __ldg(xc + ib);
            float va = dot2h(w4, Q.x, Q.y);
            float vb = dot2h(w4, Q.z, Q.w);
            bdst[jp * 72 + perm] = pack_h2(__float2half(va), __float2half(vb));
            jp += 4;
            xc += 4 * HW;
        }
    };

    gather(0, 0);
    __syncthreads();

    for (int slab = 0; slab < 36; slab++) {
        if (slab < 35) gather(slab + 1, (slab + 1) & 1);
        const unsigned* sb = s_bA[slab & 1];
#pragma unroll
        for (int kc = 0; kc < 4; kc++) {
            int kcg = slab * 4 + kc;
            const unsigned* ap = Af + (((size_t)kcg * 16 + warp * 2) * 32 + lane) * 4;
            uint4 A0 = __ldg((const uint4*)ap);
            uint4 A1 = __ldg((const uint4*)(ap + 128));

            int boff = (kc * 8 + (lane & 3)) * 72 + q * 8;
            uint4 B0a = *(const uint4*)(sb + boff);
            uint4 B0b = *(const uint4*)(sb + boff + 4);
            uint4 B1a = *(const uint4*)(sb + boff + 4 * 72);
            uint4 B1b = *(const uint4*)(sb + boff + 4 * 72 + 4);
            mma_f16(acc[0][0], A0.x, A0.y, A0.z, A0.w, B0a.x, B1a.x);
            mma_f16(acc[1][0], A1.x, A1.y, A1.z, A1.w, B0a.x, B1a.x);
            mma_f16(acc[0][1], A0.x, A0.y, A0.z, A0.w, B0a.y, B1a.y);
            mma_f16(acc[1][1], A1.x, A1.y, A1.z, A1.w, B0a.y, B1a.y);
            mma_f16(acc[0][2], A0.x, A0.y, A0.z, A0.w, B0a.z, B1a.z);
            mma_f16(acc[1][2], A1.x, A1.y, A1.z, A1.w, B0a.z, B1a.z);
            mma_f16(acc[0][3], A0.x, A0.y, A0.z, A0.w, B0a.w, B1a.w);
            mma_f16(acc[1][3], A1.x, A1.y, A1.z, A1.w, B0a.w, B1a.w);
            mma_f16(acc[0][4], A0.x, A0.y, A0.z, A0.w, B0b.x, B1b.x);
            mma_f16(acc[1][4], A1.x, A1.y, A1.z, A1.w, B0b.x, B1b.x);
            mma_f16(acc[0][5], A0.x, A0.y, A0.z, A0.w, B0b.y, B1b.y);
            mma_f16(acc[1][5], A1.x, A1.y, A1.z, A1.w, B0b.y, B1b.y);
            mma_f16(acc[0][6], A0.x, A0.y, A0.z, A0.w, B0b.z, B1b.z);
            mma_f16(acc[1][6], A1.x, A1.y, A1.z, A1.w, B0b.z, B1b.z);
            mma_f16(acc[0][7], A0.x, A0.y, A0.z, A0.w, B0b.w, B1b.w);
            mma_f16(acc[1][7], A1.x, A1.y, A1.z, A1.w, B0b.w, B1b.w);
        }
        __syncthreads();
    }

#pragma unroll
    for (int mtl = 0; mtl < 2; mtl++) {
        int o = warp * 32 + mtl * 16 + (lane >> 2);
        float b_lo = __ldg(bias + o);
        float b_hi = __ldg(bias + o + 8);
        float* o0 = out + ((size_t)b * 256 + o) * HW + tile * 64 + (lane & 3) * 2;
        float* o1 = o0 + 8 * HW;
#pragma unroll
        for (int nt = 0; nt < 8; nt++) {
            *reinterpret_cast<float2*>(o0 + nt * 8) =
                make_float2(acc[mtl][nt][0] + b_lo, acc[mtl][nt][1] + b_lo);
            *reinterpret_cast<float2*>(o1 + nt * 8) =
                make_float2(acc[mtl][nt][2] + b_hi, acc[mtl][nt][3] + b_hi);
        }
    }
}

// ---------------- host launcher ------------------------------------------------------
extern "C" void kernel_launch(void* const* d_in, const int* in_sizes, int n_in,
                              void* d_out, int out_size) {
    const float* x       = (const float*)d_in[0];
    const float* S       = (const float*)d_in[1];
    const float* sp_w1   = (const float*)d_in[2];
    const float* sp_b1   = (const float*)d_in[3];
    const float* sp_s1   = (const float*)d_in[4];
    const float* sp_o1   = (const float*)d_in[5];
    const float* sp_w2   = (const float*)d_in[6];
    const float* sp_b2   = (const float*)d_in[7];
    const float* sp_s2   = (const float*)d_in[8];
    const float* sp_o2   = (const float*)d_in[9];
    const float* sp_w3   = (const float*)d_in[10];
    const float* sp_b3   = (const float*)d_in[11];
    const float* sp_s3   = (const float*)d_in[12];
    const float* sp_o3   = (const float*)d_in[13];
    const float* off_w   = (const float*)d_in[14];
    const float* off_b   = (const float*)d_in[15];
    const float* dcoff_w = (const float*)d_in[16];
    const float* dcoff_b = (const float*)d_in[17];
    const float* dc_w    = (const float*)d_in[18];
    const float* m_w     = (const float*)d_in[19];
    const float* m_b     = (const float*)d_in[20];
    const float* weight  = (const float*)d_in[21];
    const float* bias    = (const float*)d_in[22];

    float *h1, *h2, *h3, *off, *mask, *b36;
    uint4 *xqi, *hqi3;
    unsigned *Af, *Ah2, *Al2, *Ah3, *Al3, *Ahdc, *Aldc, *Ah36, *Al36;
    cudaGetSymbolAddress((void**)&h1,   g_h1);
    cudaGetSymbolAddress((void**)&h2,   g_h2);
    cudaGetSymbolAddress((void**)&h3,   g_h3);
    cudaGetSymbolAddress((void**)&off,  g_off);
    cudaGetSymbolAddress((void**)&mask, g_mask);
    cudaGetSymbolAddress((void**)&b36,  g_b36);
    cudaGetSymbolAddress((void**)&xqi,  g_xqi);
    cudaGetSymbolAddress((void**)&hqi3, g_hqi3);
    cudaGetSymbolAddress((void**)&Af,   g_Af);
    cudaGetSymbolAddress((void**)&Ah2,  g_Ah2);
    cudaGetSymbolAddress((void**)&Al2,  g_Al2);
    cudaGetSymbolAddress((void**)&Ah3,  g_Ah3);
    cudaGetSymbolAddress((void**)&Al3,  g_Al3);
    cudaGetSymbolAddress((void**)&Ahdc, g_Ahdc);
    cudaGetSymbolAddress((void**)&Aldc, g_Aldc);
    cudaGetSymbolAddress((void**)&Ah36, g_Ah36);
    cudaGetSymbolAddress((void**)&Al36, g_Al36);

    const int SMEM_SHIFT = 2 * 3456 * 4;   // 27648
    const int SMEM_MID   = 2 * 2304 * 4;   // 18432
    cudaFuncSetAttribute(conv_shift<1>,
                         cudaFuncAttributeMaxDynamicSharedMemorySize, SMEM_SHIFT);
    cudaFuncSetAttribute(conv_shift<2>,
                         cudaFuncAttributeMaxDynamicSharedMemorySize, SMEM_SHIFT);
    cudaFuncSetAttribute(dcn_mid,
                         cudaFuncAttributeMaxDynamicSharedMemorySize, SMEM_MID);

    auto tgrid = [](int n) { return (n + 255) / 256; };
    dim3 grid(64, BATCH);

    // 0: everything input-independent in one launch (sp1 + quad_x + weight preps)
    prep_mega<<<19777, 256>>>(S, sp_w1, sp_b1, sp_s1, sp_o1, h1,
                              x, xqi,
                              sp_w2, Ah2, Al2,
                              sp_w3, Ah3, Al3,
                              off_w, dcoff_w, Ah36, Al36,
                              dc_w, Ahdc, Aldc,
                              weight, Af,
                              off_b, dcoff_b, b36);
    conv_shift<1><<<grid, 256, SMEM_SHIFT>>>(h1, Ah2, Al2,
                                             sp_b2, sp_s2, sp_o2, h2, 64);        // 1
    conv_shift<1><<<grid, 256, SMEM_SHIFT>>>(h2, Ah3, Al3,
                                             sp_b3, sp_s3, sp_o3, h3, 64);        // 2
    conv_shift<2><<<grid, 256, SMEM_SHIFT>>>(h3, Ah36, Al36,
                                             b36, nullptr, nullptr, off, 36);     // 3
    quad_h2i<<<tgrid(BATCH * 32 * HW), 256>>>(h3, hqi3, BATCH * 32 * HW, 32);     // 4
    dcn_mid<<<grid, 256, SMEM_MID>>>(hqi3, Ahdc, Aldc, off + 18 * HW, 36 * HW,
                                     m_w, m_b, mask);                             // 5
    dcn_final_f16<<<grid, 256>>>(xqi, Af, off, mask, bias, (float*)d_out);        // 6
}